// round 7
// baseline (speedup 1.0000x reference)
#include <cuda_runtime.h>
#include <math.h>

#define NNODES 10000
#define NPAD   10112      // 79 * 128
#define EDGES  80000
#define HID    1024
#define NLAYERS 4

// ---------------- scratch (static device globals: allowed) ----------------
__device__ float g_H[(size_t)NPAD * HID];            // node features (ping)
__device__ float g_S[(size_t)NPAD * HID];            // aggregated relu sums
__device__ float g_C1[(size_t)NPAD * 2 * HID];       // [A | B] per node
__device__ float g_Wcat[(size_t)NLAYERS * HID * 2 * HID]; // [W1a-W1b | W1b]
__device__ float g_G1[(size_t)NPAD * 256];           // ghost hidden
__device__ int   g_deg[NPAD];
__device__ int   g_rowptr[NNODES + 1];
__device__ int   g_cursor[NNODES];
__device__ int   g_csrsrc[EDGES];

// ---------------- helpers ----------------
__device__ __forceinline__ unsigned f2tf32(float f) {
    unsigned r;
    asm("cvt.rna.tf32.f32 %0, %1;" : "=r"(r) : "f"(f));
    return r;
}

#define MMA_TF32(d, a, b)                                              \
    asm volatile(                                                      \
        "mma.sync.aligned.m16n8k8.row.col.f32.tf32.tf32.f32 "          \
        "{%0,%1,%2,%3}, {%4,%5,%6,%7}, {%8,%9}, {%0,%1,%2,%3};\n"      \
        : "+f"(d[0]), "+f"(d[1]), "+f"(d[2]), "+f"(d[3])               \
        : "r"(a[0]), "r"(a[1]), "r"(a[2]), "r"(a[3]),                  \
          "r"(b[0]), "r"(b[1]))

// ---------------- weight prep: Wcat = [W1a - W1b | W1b] ----------------
__global__ void wcat_kernel(const float* __restrict__ W1) {
    size_t idx = (size_t)blockIdx.x * 256 + threadIdx.x;
    const size_t TOT = (size_t)NLAYERS * HID * 2 * HID;
    if (idx >= TOT) return;
    int l = (int)(idx / ((size_t)HID * 2 * HID));
    size_t rem = idx % ((size_t)HID * 2 * HID);
    int k = (int)(rem / (2 * HID));
    int j = (int)(rem % (2 * HID));
    const float* Wl = W1 + (size_t)l * 2 * HID * HID;
    float v;
    if (j < HID)
        v = Wl[(size_t)k * HID + j] - Wl[(size_t)(HID + k) * HID + j];
    else
        v = Wl[(size_t)(HID + k) * HID + (j - HID)];
    g_Wcat[idx] = v;
}

// ---------------- CSR build ----------------
__global__ void zero_deg_kernel() {
    int i = blockIdx.x * 256 + threadIdx.x;
    if (i < NPAD) g_deg[i] = 0;
}

__global__ void hist_kernel(const int* __restrict__ ei) {
    int e = blockIdx.x * 256 + threadIdx.x;
    if (e < EDGES) atomicAdd(&g_deg[ei[EDGES + e]], 1);  // dst row
}

__global__ void scan_kernel() {
    const int CH = 10;  // 1024 * 10 >= 10000
    int t = threadIdx.x;
    int base = t * CH;
    int loc[CH];
    int s = 0;
#pragma unroll
    for (int c = 0; c < CH; c++) {
        int idx = base + c;
        int v = (idx < NNODES) ? g_deg[idx] : 0;
        loc[c] = s;
        s += v;
    }
    __shared__ int sm[1024];
    sm[t] = s;
    __syncthreads();
    for (int off = 1; off < 1024; off <<= 1) {
        int v = (t >= off) ? sm[t - off] : 0;
        __syncthreads();
        sm[t] += v;
        __syncthreads();
    }
    int excl = (t > 0) ? sm[t - 1] : 0;
#pragma unroll
    for (int c = 0; c < CH; c++) {
        int idx = base + c;
        if (idx < NNODES) {
            int rp = excl + loc[c];
            g_rowptr[idx] = rp;
            g_cursor[idx] = rp;
        }
    }
    if (t == 1023) g_rowptr[NNODES] = sm[1023];
}

__global__ void scatter_kernel(const int* __restrict__ ei) {
    int e = blockIdx.x * 256 + threadIdx.x;
    if (e >= EDGES) return;
    int d = ei[EDGES + e];
    int s = ei[e];
    int p = atomicAdd(&g_cursor[d], 1);
    g_csrsrc[p] = s;
}

// ---------------- initial embedding: h = sin(x@proj_w) * cos(x@proj_w) ----------------
__global__ void proj_kernel(const float* __restrict__ x, const float* __restrict__ pw) {
    int n = blockIdx.x;
    int tid = threadIdx.x;  // 256 threads, 4 floats each
    float4* Hout = (float4*)(g_H + (size_t)n * HID);
    if (n >= NNODES) {
        Hout[tid] = make_float4(0.f, 0.f, 0.f, 0.f);
        return;
    }
    __shared__ float xs[18];
    if (tid < 18) xs[tid] = x[n * 18 + tid];
    __syncthreads();
    float4 acc = make_float4(0.f, 0.f, 0.f, 0.f);
#pragma unroll
    for (int t = 0; t < 18; t++) {
        float4 w = ((const float4*)(pw + (size_t)t * HID))[tid];
        float xv = xs[t];
        acc.x += xv * w.x;
        acc.y += xv * w.y;
        acc.z += xv * w.z;
        acc.w += xv * w.w;
    }
    float4 h;
    h.x = sinf(acc.x) * cosf(acc.x);
    h.y = sinf(acc.y) * cosf(acc.y);
    h.z = sinf(acc.z) * cosf(acc.z);
    h.w = sinf(acc.w) * cosf(acc.w);
    Hout[tid] = h;
}

// ---------------- edge aggregation: S[i] = sum_e relu(A[i] + B[src_e] + b1) ----------------
__global__ void edge_agg_kernel(const float* __restrict__ b1) {
    int i = blockIdx.x;
    int tid = threadIdx.x;  // 256 threads, 4 floats each
    float4* Sout = (float4*)(g_S + (size_t)i * HID);
    if (i >= NNODES) {
        Sout[tid] = make_float4(0.f, 0.f, 0.f, 0.f);
        return;
    }
    float4 a = ((const float4*)(g_C1 + (size_t)i * 2 * HID))[tid];
    float4 bb = ((const float4*)b1)[tid];
    a.x += bb.x; a.y += bb.y; a.z += bb.z; a.w += bb.w;
    float4 acc = make_float4(0.f, 0.f, 0.f, 0.f);
    int p0 = g_rowptr[i], p1 = g_rowptr[i + 1];
    for (int p = p0; p < p1; p++) {
        int s = g_csrsrc[p];
        float4 b = ((const float4*)(g_C1 + (size_t)s * 2 * HID + HID))[tid];
        acc.x += fmaxf(a.x + b.x, 0.f);
        acc.y += fmaxf(a.y + b.y, 0.f);
        acc.z += fmaxf(a.z + b.z, 0.f);
        acc.w += fmaxf(a.w + b.w, 0.f);
    }
    Sout[tid] = acc;
}

// ---------------- pipelined TF32 GEMM: C[M,N] = A[M,K] @ B[K,N] ----------------
// BM=128, BN=128, BK=16, 256 threads (8 warps, warp tile 64x32),
// double-buffered smem, reg-staged prefetch.
// epi: 0 = none, 2 = relu(acc + deg[m]*bias[n]), 3 = relu(acc + bias[n])
#define AS_STR 20
#define BS_STR 136

__global__ __launch_bounds__(256) void gemm_tf32_kernel(
    const float* __restrict__ A, const float* __restrict__ B, float* __restrict__ C,
    int K, int N, int epi, const float* __restrict__ bias, const int* __restrict__ deg)
{
    __shared__ float As[2][128 * AS_STR];   // [m][k] pad->20
    __shared__ float Bs[2][16 * BS_STR];    // [k][n] pad->136

    int tid = threadIdx.x;
    int warp = tid >> 5, lane = tid & 31;
    int lr = lane >> 2, lc = lane & 3;
    // 8 warps: 2 along M (64 rows each), 4 along N (32 cols each)
    int moff = (warp >> 2) * 64, noff = (warp & 3) * 32;
    int gm0 = blockIdx.y * 128, gn0 = blockIdx.x * 128;

    // per-thread load coords (256 threads, 2 float4 each for A and B)
    // A tile 128x16: idx in [0,512): r=idx>>2, c4=(idx&3)<<2
    // B tile 16x128: idx in [0,512): r=idx>>5, c4=(idx&31)<<2
    int a_r[2], a_c[2], b_r[2], b_c[2];
#pragma unroll
    for (int i = 0; i < 2; i++) {
        int idx = tid + i * 256;
        a_r[i] = idx >> 2;  a_c[i] = (idx & 3) << 2;
        b_r[i] = idx >> 5;  b_c[i] = (idx & 31) << 2;
    }

    float acc[4][4][4];
#pragma unroll
    for (int mf = 0; mf < 4; mf++)
#pragma unroll
        for (int nf = 0; nf < 4; nf++)
#pragma unroll
            for (int q = 0; q < 4; q++) acc[mf][nf][q] = 0.f;

    const int T = K >> 4;  // number of 16-wide k tiles
    float4 ra[2], rb[2];

    // prologue: load tile 0 into regs, cvt+store to stage 0
#pragma unroll
    for (int i = 0; i < 2; i++)
        ra[i] = *(const float4*)(A + (size_t)(gm0 + a_r[i]) * K + a_c[i]);
#pragma unroll
    for (int i = 0; i < 2; i++)
        rb[i] = *(const float4*)(B + (size_t)b_r[i] * N + gn0 + b_c[i]);
#pragma unroll
    for (int i = 0; i < 2; i++) {
        float* p = &As[0][a_r[i] * AS_STR + a_c[i]];
        p[0] = __uint_as_float(f2tf32(ra[i].x));
        p[1] = __uint_as_float(f2tf32(ra[i].y));
        p[2] = __uint_as_float(f2tf32(ra[i].z));
        p[3] = __uint_as_float(f2tf32(ra[i].w));
    }
#pragma unroll
    for (int i = 0; i < 2; i++) {
        float* p = &Bs[0][b_r[i] * BS_STR + b_c[i]];
        p[0] = __uint_as_float(f2tf32(rb[i].x));
        p[1] = __uint_as_float(f2tf32(rb[i].y));
        p[2] = __uint_as_float(f2tf32(rb[i].z));
        p[3] = __uint_as_float(f2tf32(rb[i].w));
    }
    __syncthreads();

    for (int kt = 0; kt < T; kt++) {
        int cur = kt & 1, nxt = cur ^ 1;
        bool more = (kt + 1 < T);

        // issue global loads for next tile (overlaps with MMAs below)
        if (more) {
            int kg = (kt + 1) << 4;
#pragma unroll
            for (int i = 0; i < 2; i++)
                ra[i] = *(const float4*)(A + (size_t)(gm0 + a_r[i]) * K + kg + a_c[i]);
#pragma unroll
            for (int i = 0; i < 2; i++)
                rb[i] = *(const float4*)(B + (size_t)(kg + b_r[i]) * N + gn0 + b_c[i]);
        }

        // compute on current stage: 2 k-slices of 8
        const float* Ac = As[cur];
        const float* Bc = Bs[cur];
#pragma unroll
        for (int ks = 0; ks < 2; ks++) {
            int kb = ks * 8;
            unsigned a[4][4], b[4][2];
#pragma unroll
            for (int mf = 0; mf < 4; mf++) {
                int r = moff + mf * 16 + lr;
                a[mf][0] = __float_as_uint(Ac[r * AS_STR + kb + lc]);
                a[mf][1] = __float_as_uint(Ac[(r + 8) * AS_STR + kb + lc]);
                a[mf][2] = __float_as_uint(Ac[r * AS_STR + kb + lc + 4]);
                a[mf][3] = __float_as_uint(Ac[(r + 8) * AS_STR + kb + lc + 4]);
            }
#pragma unroll
            for (int nf = 0; nf < 4; nf++) {
                int c = noff + nf * 8 + lr;
                b[nf][0] = __float_as_uint(Bc[(kb + lc) * BS_STR + c]);
                b[nf][1] = __float_as_uint(Bc[(kb + lc + 4) * BS_STR + c]);
            }
#pragma unroll
            for (int mf = 0; mf < 4; mf++)
#pragma unroll
                for (int nf = 0; nf < 4; nf++)
                    MMA_TF32(acc[mf][nf], a[mf], b[nf]);
        }

        // store next tile into other stage
        if (more) {
#pragma unroll
            for (int i = 0; i < 2; i++) {
                float* p = &As[nxt][a_r[i] * AS_STR + a_c[i]];
                p[0] = __uint_as_float(f2tf32(ra[i].x));
                p[1] = __uint_as_float(f2tf32(ra[i].y));
                p[2] = __uint_as_float(f2tf32(ra[i].z));
                p[3] = __uint_as_float(f2tf32(ra[i].w));
            }
#pragma unroll
            for (int i = 0; i < 2; i++) {
                float* p = &Bs[nxt][b_r[i] * BS_STR + b_c[i]];
                p[0] = __uint_as_float(f2tf32(rb[i].x));
                p[1] = __uint_as_float(f2tf32(rb[i].y));
                p[2] = __uint_as_float(f2tf32(rb[i].z));
                p[3] = __uint_as_float(f2tf32(rb[i].w));
            }
        }
        __syncthreads();
    }

    // epilogue
#pragma unroll
    for (int mf = 0; mf < 4; mf++) {
        int r = gm0 + moff + mf * 16 + lr;
        float d0 = 0.f, d1 = 0.f;
        if (epi == 2) { d0 = (float)deg[r]; d1 = (float)deg[r + 8]; }
#pragma unroll
        for (int nf = 0; nf < 4; nf++) {
            int c = gn0 + noff + nf * 8 + 2 * lc;
            float2 v0 = make_float2(acc[mf][nf][0], acc[mf][nf][1]);
            float2 v1 = make_float2(acc[mf][nf][2], acc[mf][nf][3]);
            if (epi != 0) {
                if (epi == 2) {
                    float b0 = bias[c], b1v = bias[c + 1];
                    v0.x += d0 * b0; v0.y += d0 * b1v;
                    v1.x += d1 * b0; v1.y += d1 * b1v;
                } else if (epi == 3) {
                    float b0 = bias[c], b1v = bias[c + 1];
                    v0.x += b0; v0.y += b1v;
                    v1.x += b0; v1.y += b1v;
                }
                v0.x = fmaxf(v0.x, 0.f); v0.y = fmaxf(v0.y, 0.f);
                v1.x = fmaxf(v1.x, 0.f); v1.y = fmaxf(v1.y, 0.f);
            }
            *(float2*)(C + (size_t)r * N + c) = v0;
            *(float2*)(C + (size_t)(r + 8) * N + c) = v1;
        }
    }
}

// ---------------- final heads ----------------
// out: [0,10000) ghost, [10000,190000) stable (N x 18), [190000, ...) h (N x 1024)
__global__ void final_kernel(const float* __restrict__ gw2, const float* __restrict__ gb2,
                             const float* __restrict__ sw, const float* __restrict__ sb,
                             float* __restrict__ out)
{
    int n = blockIdx.x;
    int tid = threadIdx.x;
    int lane = tid & 31, w = tid >> 5;

    // ghost score: reduce G1[n,:] * gw2
    float v = g_G1[(size_t)n * 256 + tid] * gw2[tid];
#pragma unroll
    for (int o = 16; o; o >>= 1) v += __shfl_down_sync(0xffffffffu, v, o);
    __shared__ float gs[8];
    if (lane == 0) gs[w] = v;

    // h copy + stable state partials
    float4 hv = ((const float4*)(g_H + (size_t)n * HID))[tid];
    ((float4*)(out + 190000 + (size_t)n * HID))[tid] = hv;

    int k = tid * 4;
    float sacc[18];
#pragma unroll
    for (int j = 0; j < 18; j++) {
        sacc[j] = hv.x * sw[(size_t)(k + 0) * 18 + j]
                + hv.y * sw[(size_t)(k + 1) * 18 + j]
                + hv.z * sw[(size_t)(k + 2) * 18 + j]
                + hv.w * sw[(size_t)(k + 3) * 18 + j];
    }
#pragma unroll
    for (int j = 0; j < 18; j++)
#pragma unroll
        for (int o = 16; o; o >>= 1) sacc[j] += __shfl_down_sync(0xffffffffu, sacc[j], o);

    __shared__ float sp[8][18];
    if (lane == 0)
#pragma unroll
        for (int j = 0; j < 18; j++) sp[w][j] = sacc[j];
    __syncthreads();

    if (tid == 0) {
        float g = 0.f;
#pragma unroll
        for (int i = 0; i < 8; i++) g += gs[i];
        g += gb2[0];
        out[n] = 1.f / (1.f + expf(-g));
    }
    if (tid < 18) {
        float s = sb[tid];
#pragma unroll
        for (int i = 0; i < 8; i++) s += sp[i][tid];
        out[10000 + n * 18 + tid] = s;
    }
}

// ---------------- launch ----------------
extern "C" void kernel_launch(void* const* d_in, const int* in_sizes, int n_in,
                              void* d_out, int out_size)
{
    const float* x      = (const float*)d_in[0];
    const int*   ei     = (const int*)d_in[1];
    const float* proj_w = (const float*)d_in[2];
    const float* W1     = (const float*)d_in[3];
    const float* b1     = (const float*)d_in[4];
    const float* W2     = (const float*)d_in[5];
    const float* b2     = (const float*)d_in[6];
    const float* gw1    = (const float*)d_in[7];
    const float* gb1    = (const float*)d_in[8];
    const float* gw2    = (const float*)d_in[9];
    const float* gb2    = (const float*)d_in[10];
    const float* sw     = (const float*)d_in[11];
    const float* sb     = (const float*)d_in[12];
    float* out = (float*)d_out;

    float *H, *S, *C1, *Wc, *G1;
    int* degp;
    cudaGetSymbolAddress((void**)&H, g_H);
    cudaGetSymbolAddress((void**)&S, g_S);
    cudaGetSymbolAddress((void**)&C1, g_C1);
    cudaGetSymbolAddress((void**)&Wc, g_Wcat);
    cudaGetSymbolAddress((void**)&G1, g_G1);
    cudaGetSymbolAddress((void**)&degp, g_deg);

    // weight prep + CSR build
    wcat_kernel<<<(int)(((size_t)NLAYERS * HID * 2 * HID + 255) / 256), 256>>>(W1);
    zero_deg_kernel<<<(NPAD + 255) / 256, 256>>>();
    hist_kernel<<<(EDGES + 255) / 256, 256>>>(ei);
    scan_kernel<<<1, 1024>>>();
    scatter_kernel<<<(EDGES + 255) / 256, 256>>>(ei);

    // initial embedding
    proj_kernel<<<NPAD, 256>>>(x, proj_w);

    // layers
    for (int l = 0; l < NLAYERS; l++) {
        gemm_tf32_kernel<<<dim3(2 * HID / 128, NPAD / 128), 256>>>(
            H, Wc + (size_t)l * HID * 2 * HID, C1, HID, 2 * HID, 0, nullptr, nullptr);
        edge_agg_kernel<<<NPAD, 256>>>(b1 + (size_t)l * HID);
        gemm_tf32_kernel<<<dim3(HID / 128, NPAD / 128), 256>>>(
            S, W2 + (size_t)l * HID * HID, H, HID, HID, 2, b2 + (size_t)l * HID, degp);
    }

    // ghost hidden: G1 = relu(h @ gw1 + gb1)
    gemm_tf32_kernel<<<dim3(256 / 128, NPAD / 128), 256>>>(
        H, gw1, G1, HID, 256, 3, gb1, nullptr);

    // heads + output
    final_kernel<<<NNODES, 256>>>(gw2, gb2, sw, sb, out);

    (void)in_sizes; (void)n_in; (void)out_size;
}

// round 11
// speedup vs baseline: 1.2693x; 1.2693x over previous
#include <cuda_runtime.h>
#include <cuda_fp16.h>
#include <math.h>
#include <stdint.h>

#define NNODES 10000
#define NPAD   10112      // 79 * 128
#define EDGES  80000
#define HID    1024
#define NLAYERS 4

// ---------------- scratch (static device globals: allowed) ----------------
__device__ float  g_H[(size_t)NPAD * HID];            // node features
__device__ float  g_S[(size_t)NPAD * HID];            // aggregated relu sums
__device__ float  g_C1[(size_t)NPAD * 2 * HID];       // [A | B] per node
__device__ __half g_WcatT[(size_t)NLAYERS * 2 * HID * HID]; // [l][n(2048)][k(1024)] fp16 = ([W1a-W1b | W1b])^T
__device__ __half g_W2T[(size_t)NLAYERS * HID * HID];       // [l][n][k] fp16
__device__ __half g_gw1T[(size_t)256 * HID];                // [n][k] fp16
__device__ float  g_G1[(size_t)NPAD * 256];           // ghost hidden
__device__ int    g_deg[NPAD];
__device__ int    g_rowptr[NNODES + 1];
__device__ int    g_cursor[NNODES];
__device__ int    g_csrsrc[EDGES];

// ---------------- helpers ----------------
#define MMA_F16(d, a, b)                                               \
    asm volatile(                                                      \
        "mma.sync.aligned.m16n8k16.row.col.f32.f16.f16.f32 "           \
        "{%0,%1,%2,%3}, {%4,%5,%6,%7}, {%8,%9}, {%0,%1,%2,%3};\n"      \
        : "+f"(d[0]), "+f"(d[1]), "+f"(d[2]), "+f"(d[3])               \
        : "r"(a[0]), "r"(a[1]), "r"(a[2]), "r"(a[3]),                  \
          "r"(b[0]), "r"(b[1]))

// ---------------- weight prep: transposed + fp16 ----------------
// WcatT[l][j][k] = (j<HID) ? W1[l][k][j] - W1[l][HID+k][j] : W1[l][HID+k][j-HID]
__global__ void wcatT_kernel(const float* __restrict__ W1) {
    __shared__ float t[32][33];
    int l = blockIdx.z;
    int j0 = blockIdx.x * 32, k0 = blockIdx.y * 32;
    const float* Wl = W1 + (size_t)l * 2 * HID * HID;
    int tx = threadIdx.x, ty = threadIdx.y;
    for (int kk = ty; kk < 32; kk += 8) {
        int k = k0 + kk, j = j0 + tx;
        float v;
        if (j < HID) v = Wl[(size_t)k * HID + j] - Wl[(size_t)(HID + k) * HID + j];
        else         v = Wl[(size_t)(HID + k) * HID + (j - HID)];
        t[kk][tx] = v;
    }
    __syncthreads();
    __half* dst = g_WcatT + (size_t)l * 2 * HID * HID;
    for (int jj = ty; jj < 32; jj += 8)
        dst[(size_t)(j0 + jj) * HID + k0 + tx] = __float2half_rn(t[tx][jj]);
}

__global__ void w2T_kernel(const float* __restrict__ W2) {
    __shared__ float t[32][33];
    int l = blockIdx.z;
    int n0 = blockIdx.x * 32, k0 = blockIdx.y * 32;
    const float* Wl = W2 + (size_t)l * HID * HID;
    int tx = threadIdx.x, ty = threadIdx.y;
    for (int kk = ty; kk < 32; kk += 8)
        t[kk][tx] = Wl[(size_t)(k0 + kk) * HID + n0 + tx];
    __syncthreads();
    __half* dst = g_W2T + (size_t)l * HID * HID;
    for (int nn = ty; nn < 32; nn += 8)
        dst[(size_t)(n0 + nn) * HID + k0 + tx] = __float2half_rn(t[tx][nn]);
}

__global__ void gw1T_kernel(const float* __restrict__ gw1) {
    __shared__ float t[32][33];
    int n0 = blockIdx.x * 32, k0 = blockIdx.y * 32;
    int tx = threadIdx.x, ty = threadIdx.y;
    for (int kk = ty; kk < 32; kk += 8)
        t[kk][tx] = gw1[(size_t)(k0 + kk) * 256 + n0 + tx];
    __syncthreads();
    for (int nn = ty; nn < 32; nn += 8)
        g_gw1T[(size_t)(n0 + nn) * HID + k0 + tx] = __float2half_rn(t[tx][nn]);
}

// ---------------- CSR build ----------------
__global__ void zero_deg_kernel() {
    int i = blockIdx.x * 256 + threadIdx.x;
    if (i < NPAD) g_deg[i] = 0;
}

__global__ void hist_kernel(const int* __restrict__ ei) {
    int e = blockIdx.x * 256 + threadIdx.x;
    if (e < EDGES) atomicAdd(&g_deg[ei[EDGES + e]], 1);
}

__global__ void scan_kernel() {
    const int CH = 10;
    int t = threadIdx.x;
    int base = t * CH;
    int loc[CH];
    int s = 0;
#pragma unroll
    for (int c = 0; c < CH; c++) {
        int idx = base + c;
        int v = (idx < NNODES) ? g_deg[idx] : 0;
        loc[c] = s;
        s += v;
    }
    __shared__ int sm[1024];
    sm[t] = s;
    __syncthreads();
    for (int off = 1; off < 1024; off <<= 1) {
        int v = (t >= off) ? sm[t - off] : 0;
        __syncthreads();
        sm[t] += v;
        __syncthreads();
    }
    int excl = (t > 0) ? sm[t - 1] : 0;
#pragma unroll
    for (int c = 0; c < CH; c++) {
        int idx = base + c;
        if (idx < NNODES) {
            int rp = excl + loc[c];
            g_rowptr[idx] = rp;
            g_cursor[idx] = rp;
        }
    }
    if (t == 1023) g_rowptr[NNODES] = sm[1023];
}

__global__ void scatter_kernel(const int* __restrict__ ei) {
    int e = blockIdx.x * 256 + threadIdx.x;
    if (e >= EDGES) return;
    int d = ei[EDGES + e];
    int s = ei[e];
    int p = atomicAdd(&g_cursor[d], 1);
    g_csrsrc[p] = s;
}

// ---------------- initial embedding ----------------
__global__ void proj_kernel(const float* __restrict__ x, const float* __restrict__ pw) {
    int n = blockIdx.x;
    int tid = threadIdx.x;
    float4* Hout = (float4*)(g_H + (size_t)n * HID);
    if (n >= NNODES) {
        Hout[tid] = make_float4(0.f, 0.f, 0.f, 0.f);
        return;
    }
    __shared__ float xs[18];
    if (tid < 18) xs[tid] = x[n * 18 + tid];
    __syncthreads();
    float4 acc = make_float4(0.f, 0.f, 0.f, 0.f);
#pragma unroll
    for (int t = 0; t < 18; t++) {
        float4 w = ((const float4*)(pw + (size_t)t * HID))[tid];
        float xv = xs[t];
        acc.x += xv * w.x;
        acc.y += xv * w.y;
        acc.z += xv * w.z;
        acc.w += xv * w.w;
    }
    float4 h;
    h.x = sinf(acc.x) * cosf(acc.x);
    h.y = sinf(acc.y) * cosf(acc.y);
    h.z = sinf(acc.z) * cosf(acc.z);
    h.w = sinf(acc.w) * cosf(acc.w);
    Hout[tid] = h;
}

// ---------------- edge aggregation ----------------
__global__ void edge_agg_kernel(const float* __restrict__ b1) {
    int i = blockIdx.x;
    int tid = threadIdx.x;
    float4* Sout = (float4*)(g_S + (size_t)i * HID);
    if (i >= NNODES) {
        Sout[tid] = make_float4(0.f, 0.f, 0.f, 0.f);
        return;
    }
    float4 a = ((const float4*)(g_C1 + (size_t)i * 2 * HID))[tid];
    float4 bb = ((const float4*)b1)[tid];
    a.x += bb.x; a.y += bb.y; a.z += bb.z; a.w += bb.w;
    float4 acc = make_float4(0.f, 0.f, 0.f, 0.f);
    int p0 = g_rowptr[i], p1 = g_rowptr[i + 1];
    for (int p = p0; p < p1; p++) {
        int s = g_csrsrc[p];
        float4 b = ((const float4*)(g_C1 + (size_t)s * 2 * HID + HID))[tid];
        acc.x += fmaxf(a.x + b.x, 0.f);
        acc.y += fmaxf(a.y + b.y, 0.f);
        acc.z += fmaxf(a.z + b.z, 0.f);
        acc.w += fmaxf(a.w + b.w, 0.f);
    }
    Sout[tid] = acc;
}

// ---------------- fp16 GEMM: C[M,N] = A[M,K] @ BT[N,K]^T ----------------
// BM=128, BN=128, BK=32 (2 k16 slices), 256 threads (8 warps, warp tile 64x32),
// double-buffered padded smem, reg-staged prefetch, fp32 accumulate.
// epi: 0 = none, 2 = relu(acc + deg[m]*bias[n]), 3 = relu(acc + bias[n])
#define HSTR 40   // halfs per smem row (32 data + 8 pad) -> conflict-free frags

__global__ __launch_bounds__(256) void gemm_f16_kernel(
    const float* __restrict__ A, const __half* __restrict__ BT, float* __restrict__ C,
    int K, int N, int epi, const float* __restrict__ bias, const int* __restrict__ deg)
{
    __shared__ __half As[2][128 * HSTR];   // 10KB per stage
    __shared__ __half Bs[2][128 * HSTR];   // 10KB per stage

    int tid = threadIdx.x;
    int warp = tid >> 5, lane = tid & 31;
    int lr = lane >> 2, lc = lane & 3;
    int moff = (warp >> 2) * 64, noff = (warp & 3) * 32;
    int gm0 = blockIdx.y * 128, gn0 = blockIdx.x * 128;

    // load coords: tile is 128 rows x 32 cols; 8 chunks of 4 per row -> 1024 chunks,
    // 256 threads x 4 chunks each. r = idx>>3, c4 = (idx&7)*4
    int rr[4], cc[4];
#pragma unroll
    for (int i = 0; i < 4; i++) {
        int idx = tid + i * 256;
        rr[i] = idx >> 3;
        cc[i] = (idx & 7) << 2;
    }

    float acc[4][4][4];
#pragma unroll
    for (int mf = 0; mf < 4; mf++)
#pragma unroll
        for (int nf = 0; nf < 4; nf++)
#pragma unroll
            for (int q = 0; q < 4; q++) acc[mf][nf][q] = 0.f;

    const int T = K >> 5;  // K=1024 -> 32 tiles
    float4 ra[4];
    uint2  rb[4];

    // prologue: tile 0 -> regs -> stage 0
#pragma unroll
    for (int i = 0; i < 4; i++)
        ra[i] = *(const float4*)(A + (size_t)(gm0 + rr[i]) * K + cc[i]);
#pragma unroll
    for (int i = 0; i < 4; i++)
        rb[i] = *(const uint2*)(BT + (size_t)(gn0 + rr[i]) * K + cc[i]);
#pragma unroll
    for (int i = 0; i < 4; i++) {
        __half2* p = (__half2*)&As[0][rr[i] * HSTR + cc[i]];
        p[0] = __floats2half2_rn(ra[i].x, ra[i].y);
        p[1] = __floats2half2_rn(ra[i].z, ra[i].w);
        *(uint2*)&Bs[0][rr[i] * HSTR + cc[i]] = rb[i];
    }
    __syncthreads();

    for (int kt = 0; kt < T; kt++) {
        int cur = kt & 1, nxt = cur ^ 1;
        bool more = (kt + 1 < T);

        if (more) {
            int kg = (kt + 1) << 5;
#pragma unroll
            for (int i = 0; i < 4; i++)
                ra[i] = *(const float4*)(A + (size_t)(gm0 + rr[i]) * K + kg + cc[i]);
#pragma unroll
            for (int i = 0; i < 4; i++)
                rb[i] = *(const uint2*)(BT + (size_t)(gn0 + rr[i]) * K + kg + cc[i]);
        }

        const __half* Ac = As[cur];
        const __half* Bc = Bs[cur];
#pragma unroll
        for (int ks = 0; ks < 2; ks++) {
            int kb = ks * 16;  // halfs
            unsigned a[4][4], b[4][2];
#pragma unroll
            for (int mf = 0; mf < 4; mf++) {
                int r = moff + mf * 16 + lr;
                a[mf][0] = *(const unsigned*)&Ac[r * HSTR + kb + 2 * lc];
                a[mf][1] = *(const unsigned*)&Ac[(r + 8) * HSTR + kb + 2 * lc];
                a[mf][2] = *(const unsigned*)&Ac[r * HSTR + kb + 2 * lc + 8];
                a[mf][3] = *(const unsigned*)&Ac[(r + 8) * HSTR + kb + 2 * lc + 8];
            }
#pragma unroll
            for (int nf = 0; nf < 4; nf++) {
                int c = noff + nf * 8 + lr;
                b[nf][0] = *(const unsigned*)&Bc[c * HSTR + kb + 2 * lc];
                b[nf][1] = *(const unsigned*)&Bc[c * HSTR + kb + 2 * lc + 8];
            }
#pragma unroll
            for (int mf = 0; mf < 4; mf++)
#pragma unroll
                for (int nf = 0; nf < 4; nf++)
                    MMA_F16(acc[mf][nf], a[mf], b[nf]);
        }

        if (more) {
#pragma unroll
            for (int i = 0; i < 4; i++) {
                __half2* p = (__half2*)&As[nxt][rr[i] * HSTR + cc[i]];
                p[0] = __floats2half2_rn(ra[i].x, ra[i].y);
                p[1] = __floats2half2_rn(ra[i].z, ra[i].w);
                *(uint2*)&Bs[nxt][rr[i] * HSTR + cc[i]] = rb[i];
            }
        }
        __syncthreads();
    }

    // epilogue
#pragma unroll
    for (int mf = 0; mf < 4; mf++) {
        int r = gm0 + moff + mf * 16 + lr;
        float d0 = 0.f, d1 = 0.f;
        if (epi == 2) { d0 = (float)deg[r]; d1 = (float)deg[r + 8]; }
#pragma unroll
        for (int nf = 0; nf < 4; nf++) {
            int c = gn0 + noff + nf * 8 + 2 * lc;
            float2 v0 = make_float2(acc[mf][nf][0], acc[mf][nf][1]);
            float2 v1 = make_float2(acc[mf][nf][2], acc[mf][nf][3]);
            if (epi != 0) {
                float b0 = bias[c], b1v = bias[c + 1];
                if (epi == 2) {
                    v0.x += d0 * b0; v0.y += d0 * b1v;
                    v1.x += d1 * b0; v1.y += d1 * b1v;
                } else {
                    v0.x += b0; v0.y += b1v;
                    v1.x += b0; v1.y += b1v;
                }
                v0.x = fmaxf(v0.x, 0.f); v0.y = fmaxf(v0.y, 0.f);
                v1.x = fmaxf(v1.x, 0.f); v1.y = fmaxf(v1.y, 0.f);
            }
            *(float2*)(C + (size_t)r * N + c) = v0;
            *(float2*)(C + (size_t)(r + 8) * N + c) = v1;
        }
    }
}

// ---------------- final heads ----------------
// out: [0,10000) ghost, [10000,190000) stable (N x 18), [190000,...) h (N x 1024)
__global__ void final_kernel(const float* __restrict__ gw2, const float* __restrict__ gb2,
                             const float* __restrict__ sw, const float* __restrict__ sb,
                             float* __restrict__ out)
{
    int n = blockIdx.x;
    int tid = threadIdx.x;
    int lane = tid & 31, w = tid >> 5;

    float v = g_G1[(size_t)n * 256 + tid] * gw2[tid];
#pragma unroll
    for (int o = 16; o; o >>= 1) v += __shfl_down_sync(0xffffffffu, v, o);
    __shared__ float gs[8];
    if (lane == 0) gs[w] = v;

    float4 hv = ((const float4*)(g_H + (size_t)n * HID))[tid];
    ((float4*)(out + 190000 + (size_t)n * HID))[tid] = hv;

    int k = tid * 4;
    float sacc[18];
#pragma unroll
    for (int j = 0; j < 18; j++) {
        sacc[j] = hv.x * sw[(size_t)(k + 0) * 18 + j]
                + hv.y * sw[(size_t)(k + 1) * 18 + j]
                + hv.z * sw[(size_t)(k + 2) * 18 + j]
                + hv.w * sw[(size_t)(k + 3) * 18 + j];
    }
#pragma unroll
    for (int j = 0; j < 18; j++)
#pragma unroll
        for (int o = 16; o; o >>= 1) sacc[j] += __shfl_down_sync(0xffffffffu, sacc[j], o);

    __shared__ float sp[8][18];
    if (lane == 0)
#pragma unroll
        for (int j = 0; j < 18; j++) sp[w][j] = sacc[j];
    __syncthreads();

    if (tid == 0) {
        float g = 0.f;
#pragma unroll
        for (int i = 0; i < 8; i++) g += gs[i];
        g += gb2[0];
        out[n] = 1.f / (1.f + expf(-g));
    }
    if (tid < 18) {
        float s = sb[tid];
#pragma unroll
        for (int i = 0; i < 8; i++) s += sp[i][tid];
        out[10000 + n * 18 + tid] = s;
    }
}

// ---------------- launch ----------------
extern "C" void kernel_launch(void* const* d_in, const int* in_sizes, int n_in,
                              void* d_out, int out_size)
{
    const float* x      = (const float*)d_in[0];
    const int*   ei     = (const int*)d_in[1];
    const float* proj_w = (const float*)d_in[2];
    const float* W1     = (const float*)d_in[3];
    const float* b1     = (const float*)d_in[4];
    const float* W2     = (const float*)d_in[5];
    const float* b2     = (const float*)d_in[6];
    const float* gw1    = (const float*)d_in[7];
    const float* gb1    = (const float*)d_in[8];
    const float* gw2    = (const float*)d_in[9];
    const float* gb2    = (const float*)d_in[10];
    const float* sw     = (const float*)d_in[11];
    const float* sb     = (const float*)d_in[12];
    float* out = (float*)d_out;

    float *H, *S, *C1, *G1;
    __half *WcT, *W2T, *G1T;
    int* degp;
    cudaGetSymbolAddress((void**)&H, g_H);
    cudaGetSymbolAddress((void**)&S, g_S);
    cudaGetSymbolAddress((void**)&C1, g_C1);
    cudaGetSymbolAddress((void**)&WcT, g_WcatT);
    cudaGetSymbolAddress((void**)&W2T, g_W2T);
    cudaGetSymbolAddress((void**)&G1T, g_gw1T);
    cudaGetSymbolAddress((void**)&G1, g_G1);
    cudaGetSymbolAddress((void**)&degp, g_deg);

    // weight prep (transpose + fp16) + CSR build
    wcatT_kernel<<<dim3(2 * HID / 32, HID / 32, NLAYERS), dim3(32, 8)>>>(W1);
    w2T_kernel<<<dim3(HID / 32, HID / 32, NLAYERS), dim3(32, 8)>>>(W2);
    gw1T_kernel<<<dim3(256 / 32, HID / 32), dim3(32, 8)>>>(gw1);
    zero_deg_kernel<<<(NPAD + 255) / 256, 256>>>();
    hist_kernel<<<(EDGES + 255) / 256, 256>>>(ei);
    scan_kernel<<<1, 1024>>>();
    scatter_kernel<<<(EDGES + 255) / 256, 256>>>(ei);

    // initial embedding
    proj_kernel<<<NPAD, 256>>>(x, proj_w);

    // layers
    for (int l = 0; l < NLAYERS; l++) {
        gemm_f16_kernel<<<dim3(2 * HID / 128, NPAD / 128), 256>>>(
            H, WcT + (size_t)l * 2 * HID * HID, C1, HID, 2 * HID, 0, nullptr, nullptr);
        edge_agg_kernel<<<NPAD, 256>>>(b1 + (size_t)l * HID);
        gemm_f16_kernel<<<dim3(HID / 128, NPAD / 128), 256>>>(
            S, W2T + (size_t)l * HID * HID, H, HID, HID, 2, b2 + (size_t)l * HID, degp);
    }

    // ghost hidden: G1 = relu(h @ gw1 + gb1)
    gemm_f16_kernel<<<dim3(256 / 128, NPAD / 128), 256>>>(
        H, G1T, G1, HID, 256, 3, gb1, nullptr);

    // heads + output
    final_kernel<<<NNODES, 256>>>(gw2, gb2, sw, sb, out);

    (void)in_sizes; (void)n_in; (void)out_size;
}

// round 14
// speedup vs baseline: 1.5852x; 1.2489x over previous
#include <cuda_runtime.h>
#include <cuda_fp16.h>
#include <math.h>
#include <stdint.h>

#define NNODES 10000
#define NPAD   10112      // 79 * 128
#define EDGES  80000
#define HID    1024
#define NLAYERS 4

// ---------------- scratch (static device globals: allowed) ----------------
__device__ float  g_H[(size_t)NPAD * HID];            // node features fp32 (output + heads)
__device__ __half g_Hh[(size_t)NPAD * HID];           // fp16 mirror of H (GEMM A operand)
__device__ __half g_Sh[(size_t)NPAD * HID];           // aggregated relu sums, fp16 (GEMM A operand)
__device__ float  g_C1[(size_t)NPAD * 2 * HID];       // [A | B] per node (fp32, feeds edge sums)
__device__ __half g_WcatT[(size_t)NLAYERS * 2 * HID * HID]; // [l][n(2048)][k(1024)] fp16 = ([W1a-W1b | W1b])^T
__device__ __half g_W2T[(size_t)NLAYERS * HID * HID];       // [l][n][k] fp16
__device__ __half g_gw1T[(size_t)256 * HID];                // [n][k] fp16
__device__ float  g_G1[(size_t)NPAD * 256];           // ghost hidden
__device__ int    g_deg[NPAD];
__device__ int    g_rowptr[NNODES + 1];
__device__ int    g_cursor[NNODES];
__device__ int    g_csrsrc[EDGES];

// ---------------- helpers ----------------
#define MMA_F16(d, a, b)                                               \
    asm volatile(                                                      \
        "mma.sync.aligned.m16n8k16.row.col.f32.f16.f16.f32 "           \
        "{%0,%1,%2,%3}, {%4,%5,%6,%7}, {%8,%9}, {%0,%1,%2,%3};\n"      \
        : "+f"(d[0]), "+f"(d[1]), "+f"(d[2]), "+f"(d[3])               \
        : "r"(a[0]), "r"(a[1]), "r"(a[2]), "r"(a[3]),                  \
          "r"(b[0]), "r"(b[1]))

// ---------------- weight prep: transposed + fp16 ----------------
// WcatT[l][j][k] = (j<HID) ? W1[l][k][j] - W1[l][HID+k][j] : W1[l][HID+k][j-HID]
__global__ void wcatT_kernel(const float* __restrict__ W1) {
    __shared__ float t[32][33];
    int l = blockIdx.z;
    int j0 = blockIdx.x * 32, k0 = blockIdx.y * 32;
    const float* Wl = W1 + (size_t)l * 2 * HID * HID;
    int tx = threadIdx.x, ty = threadIdx.y;
    for (int kk = ty; kk < 32; kk += 8) {
        int k = k0 + kk, j = j0 + tx;
        float v;
        if (j < HID) v = Wl[(size_t)k * HID + j] - Wl[(size_t)(HID + k) * HID + j];
        else         v = Wl[(size_t)(HID + k) * HID + (j - HID)];
        t[kk][tx] = v;
    }
    __syncthreads();
    __half* dst = g_WcatT + (size_t)l * 2 * HID * HID;
    for (int jj = ty; jj < 32; jj += 8)
        dst[(size_t)(j0 + jj) * HID + k0 + tx] = __float2half_rn(t[tx][jj]);
}

__global__ void w2T_kernel(const float* __restrict__ W2) {
    __shared__ float t[32][33];
    int l = blockIdx.z;
    int n0 = blockIdx.x * 32, k0 = blockIdx.y * 32;
    const float* Wl = W2 + (size_t)l * HID * HID;
    int tx = threadIdx.x, ty = threadIdx.y;
    for (int kk = ty; kk < 32; kk += 8)
        t[kk][tx] = Wl[(size_t)(k0 + kk) * HID + n0 + tx];
    __syncthreads();
    __half* dst = g_W2T + (size_t)l * HID * HID;
    for (int nn = ty; nn < 32; nn += 8)
        dst[(size_t)(n0 + nn) * HID + k0 + tx] = __float2half_rn(t[tx][nn]);
}

__global__ void gw1T_kernel(const float* __restrict__ gw1) {
    __shared__ float t[32][33];
    int n0 = blockIdx.x * 32, k0 = blockIdx.y * 32;
    int tx = threadIdx.x, ty = threadIdx.y;
    for (int kk = ty; kk < 32; kk += 8)
        t[kk][tx] = gw1[(size_t)(k0 + kk) * 256 + n0 + tx];
    __syncthreads();
    for (int nn = ty; nn < 32; nn += 8)
        g_gw1T[(size_t)(n0 + nn) * HID + k0 + tx] = __float2half_rn(t[tx][nn]);
}

// ---------------- CSR build ----------------
__global__ void zero_deg_kernel() {
    int i = blockIdx.x * 256 + threadIdx.x;
    if (i < NPAD) g_deg[i] = 0;
}

__global__ void hist_kernel(const int* __restrict__ ei) {
    int e = blockIdx.x * 256 + threadIdx.x;
    if (e < EDGES) atomicAdd(&g_deg[ei[EDGES + e]], 1);
}

__global__ void scan_kernel() {
    const int CH = 10;
    int t = threadIdx.x;
    int base = t * CH;
    int loc[CH];
    int s = 0;
#pragma unroll
    for (int c = 0; c < CH; c++) {
        int idx = base + c;
        int v = (idx < NNODES) ? g_deg[idx] : 0;
        loc[c] = s;
        s += v;
    }
    __shared__ int sm[1024];
    sm[t] = s;
    __syncthreads();
    for (int off = 1; off < 1024; off <<= 1) {
        int v = (t >= off) ? sm[t - off] : 0;
        __syncthreads();
        sm[t] += v;
        __syncthreads();
    }
    int excl = (t > 0) ? sm[t - 1] : 0;
#pragma unroll
    for (int c = 0; c < CH; c++) {
        int idx = base + c;
        if (idx < NNODES) {
            int rp = excl + loc[c];
            g_rowptr[idx] = rp;
            g_cursor[idx] = rp;
        }
    }
    if (t == 1023) g_rowptr[NNODES] = sm[1023];
}

__global__ void scatter_kernel(const int* __restrict__ ei) {
    int e = blockIdx.x * 256 + threadIdx.x;
    if (e >= EDGES) return;
    int d = ei[EDGES + e];
    int s = ei[e];
    int p = atomicAdd(&g_cursor[d], 1);
    g_csrsrc[p] = s;
}

// ---------------- initial embedding ----------------
__global__ void proj_kernel(const float* __restrict__ x, const float* __restrict__ pw) {
    int n = blockIdx.x;
    int tid = threadIdx.x;
    float4* Hout = (float4*)(g_H + (size_t)n * HID);
    __half2* Hh = (__half2*)(g_Hh + (size_t)n * HID) + tid * 2;
    if (n >= NNODES) {
        Hout[tid] = make_float4(0.f, 0.f, 0.f, 0.f);
        Hh[0] = __half2half2(__float2half_rn(0.f));
        Hh[1] = __half2half2(__float2half_rn(0.f));
        return;
    }
    __shared__ float xs[18];
    if (tid < 18) xs[tid] = x[n * 18 + tid];
    __syncthreads();
    float4 acc = make_float4(0.f, 0.f, 0.f, 0.f);
#pragma unroll
    for (int t = 0; t < 18; t++) {
        float4 w = ((const float4*)(pw + (size_t)t * HID))[tid];
        float xv = xs[t];
        acc.x += xv * w.x;
        acc.y += xv * w.y;
        acc.z += xv * w.z;
        acc.w += xv * w.w;
    }
    float4 h;
    h.x = sinf(acc.x) * cosf(acc.x);
    h.y = sinf(acc.y) * cosf(acc.y);
    h.z = sinf(acc.z) * cosf(acc.z);
    h.w = sinf(acc.w) * cosf(acc.w);
    Hout[tid] = h;
    Hh[0] = __floats2half2_rn(h.x, h.y);
    Hh[1] = __floats2half2_rn(h.z, h.w);
}

// ---------------- edge aggregation: Sh[i] = fp16( sum_e relu(A[i] + B[src_e] + b1) ) ----------------
__global__ void edge_agg_kernel(const float* __restrict__ b1) {
    int i = blockIdx.x;
    int tid = threadIdx.x;
    __half2* Sout = (__half2*)(g_Sh + (size_t)i * HID) + tid * 2;
    if (i >= NNODES) {
        Sout[0] = __half2half2(__float2half_rn(0.f));
        Sout[1] = __half2half2(__float2half_rn(0.f));
        return;
    }
    float4 a = ((const float4*)(g_C1 + (size_t)i * 2 * HID))[tid];
    float4 bb = ((const float4*)b1)[tid];
    a.x += bb.x; a.y += bb.y; a.z += bb.z; a.w += bb.w;
    float4 acc = make_float4(0.f, 0.f, 0.f, 0.f);
    int p0 = g_rowptr[i], p1 = g_rowptr[i + 1];
    for (int p = p0; p < p1; p++) {
        int s = g_csrsrc[p];
        float4 b = ((const float4*)(g_C1 + (size_t)s * 2 * HID + HID))[tid];
        acc.x += fmaxf(a.x + b.x, 0.f);
        acc.y += fmaxf(a.y + b.y, 0.f);
        acc.z += fmaxf(a.z + b.z, 0.f);
        acc.w += fmaxf(a.w + b.w, 0.f);
    }
    Sout[0] = __floats2half2_rn(acc.x, acc.y);
    Sout[1] = __floats2half2_rn(acc.z, acc.w);
}

// ---------------- fp16 GEMM: C[M,N] = A[M,K] @ BT[N,K]^T ----------------
// A and BT both fp16 K-major. BM=128, BN=128, BK=32 (2 k16 slices), 256 threads
// (8 warps, warp tile 64x32), double-buffered padded smem, fp32 accumulate.
// epi: 0 = none, 2 = relu(acc + deg[m]*bias[n]) [+ fp16 mirror Ch], 3 = relu(acc + bias[n])
#define HSTR 40   // halfs per smem row (32 data + 8 pad) -> conflict-free frags

__global__ __launch_bounds__(256) void gemm_f16_kernel(
    const __half* __restrict__ A, const __half* __restrict__ BT,
    float* __restrict__ C, __half* __restrict__ Ch,
    int K, int N, int epi, const float* __restrict__ bias, const int* __restrict__ deg)
{
    __shared__ __half As[2][128 * HSTR];   // 10KB per stage
    __shared__ __half Bs[2][128 * HSTR];   // 10KB per stage

    int tid = threadIdx.x;
    int warp = tid >> 5, lane = tid & 31;
    int lr = lane >> 2, lc = lane & 3;
    int moff = (warp >> 2) * 64, noff = (warp & 3) * 32;
    int gm0 = blockIdx.y * 128, gn0 = blockIdx.x * 128;

    // load coords: tile is 128 rows x 32 halfs; 256 threads x 4 chunks of 4 halfs (8B)
    int rr[4], cc[4];
#pragma unroll
    for (int i = 0; i < 4; i++) {
        int idx = tid + i * 256;
        rr[i] = idx >> 3;
        cc[i] = (idx & 7) << 2;
    }

    float acc[4][4][4];
#pragma unroll
    for (int mf = 0; mf < 4; mf++)
#pragma unroll
        for (int nf = 0; nf < 4; nf++)
#pragma unroll
            for (int q = 0; q < 4; q++) acc[mf][nf][q] = 0.f;

    const int T = K >> 5;  // K=1024 -> 32 tiles
    uint2 ra[4], rb[4];

    // prologue: tile 0 -> regs -> stage 0
#pragma unroll
    for (int i = 0; i < 4; i++)
        ra[i] = *(const uint2*)(A + (size_t)(gm0 + rr[i]) * K + cc[i]);
#pragma unroll
    for (int i = 0; i < 4; i++)
        rb[i] = *(const uint2*)(BT + (size_t)(gn0 + rr[i]) * K + cc[i]);
#pragma unroll
    for (int i = 0; i < 4; i++) {
        *(uint2*)&As[0][rr[i] * HSTR + cc[i]] = ra[i];
        *(uint2*)&Bs[0][rr[i] * HSTR + cc[i]] = rb[i];
    }
    __syncthreads();

    for (int kt = 0; kt < T; kt++) {
        int cur = kt & 1, nxt = cur ^ 1;
        bool more = (kt + 1 < T);

        if (more) {
            int kg = (kt + 1) << 5;
#pragma unroll
            for (int i = 0; i < 4; i++)
                ra[i] = *(const uint2*)(A + (size_t)(gm0 + rr[i]) * K + kg + cc[i]);
#pragma unroll
            for (int i = 0; i < 4; i++)
                rb[i] = *(const uint2*)(BT + (size_t)(gn0 + rr[i]) * K + kg + cc[i]);
        }

        const __half* Ac = As[cur];
        const __half* Bc = Bs[cur];
#pragma unroll
        for (int ks = 0; ks < 2; ks++) {
            int kb = ks * 16;  // halfs
            unsigned a[4][4], b[4][2];
#pragma unroll
            for (int mf = 0; mf < 4; mf++) {
                int r = moff + mf * 16 + lr;
                a[mf][0] = *(const unsigned*)&Ac[r * HSTR + kb + 2 * lc];
                a[mf][1] = *(const unsigned*)&Ac[(r + 8) * HSTR + kb + 2 * lc];
                a[mf][2] = *(const unsigned*)&Ac[r * HSTR + kb + 2 * lc + 8];
                a[mf][3] = *(const unsigned*)&Ac[(r + 8) * HSTR + kb + 2 * lc + 8];
            }
#pragma unroll
            for (int nf = 0; nf < 4; nf++) {
                int c = noff + nf * 8 + lr;
                b[nf][0] = *(const unsigned*)&Bc[c * HSTR + kb + 2 * lc];
                b[nf][1] = *(const unsigned*)&Bc[c * HSTR + kb + 2 * lc + 8];
            }
#pragma unroll
            for (int mf = 0; mf < 4; mf++)
#pragma unroll
                for (int nf = 0; nf < 4; nf++)
                    MMA_F16(acc[mf][nf], a[mf], b[nf]);
        }

        if (more) {
#pragma unroll
            for (int i = 0; i < 4; i++) {
                *(uint2*)&As[nxt][rr[i] * HSTR + cc[i]] = ra[i];
                *(uint2*)&Bs[nxt][rr[i] * HSTR + cc[i]] = rb[i];
            }
        }
        __syncthreads();
    }

    // epilogue
#pragma unroll
    for (int mf = 0; mf < 4; mf++) {
        int r = gm0 + moff + mf * 16 + lr;
        float d0 = 0.f, d1 = 0.f;
        if (epi == 2) { d0 = (float)deg[r]; d1 = (float)deg[r + 8]; }
#pragma unroll
        for (int nf = 0; nf < 4; nf++) {
            int c = gn0 + noff + nf * 8 + 2 * lc;
            float2 v0 = make_float2(acc[mf][nf][0], acc[mf][nf][1]);
            float2 v1 = make_float2(acc[mf][nf][2], acc[mf][nf][3]);
            if (epi != 0) {
                float b0 = bias[c], b1v = bias[c + 1];
                if (epi == 2) {
                    v0.x += d0 * b0; v0.y += d0 * b1v;
                    v1.x += d1 * b0; v1.y += d1 * b1v;
                } else {
                    v0.x += b0; v0.y += b1v;
                    v1.x += b0; v1.y += b1v;
                }
                v0.x = fmaxf(v0.x, 0.f); v0.y = fmaxf(v0.y, 0.f);
                v1.x = fmaxf(v1.x, 0.f); v1.y = fmaxf(v1.y, 0.f);
            }
            *(float2*)(C + (size_t)r * N + c) = v0;
            *(float2*)(C + (size_t)(r + 8) * N + c) = v1;
            if (epi == 2) {
                *(__half2*)(Ch + (size_t)r * N + c) = __floats2half2_rn(v0.x, v0.y);
                *(__half2*)(Ch + (size_t)(r + 8) * N + c) = __floats2half2_rn(v1.x, v1.y);
            }
        }
    }
}

// ---------------- final heads ----------------
// out: [0,10000) ghost, [10000,190000) stable (N x 18), [190000,...) h (N x 1024)
__global__ void final_kernel(const float* __restrict__ gw2, const float* __restrict__ gb2,
                             const float* __restrict__ sw, const float* __restrict__ sb,
                             float* __restrict__ out)
{
    int n = blockIdx.x;
    int tid = threadIdx.x;
    int lane = tid & 31, w = tid >> 5;

    float v = g_G1[(size_t)n * 256 + tid] * gw2[tid];
#pragma unroll
    for (int o = 16; o; o >>= 1) v += __shfl_down_sync(0xffffffffu, v, o);
    __shared__ float gs[8];
    if (lane == 0) gs[w] = v;

    float4 hv = ((const float4*)(g_H + (size_t)n * HID))[tid];
    ((float4*)(out + 190000 + (size_t)n * HID))[tid] = hv;

    int k = tid * 4;
    float sacc[18];
#pragma unroll
    for (int j = 0; j < 18; j++) {
        sacc[j] = hv.x * sw[(size_t)(k + 0) * 18 + j]
                + hv.y * sw[(size_t)(k + 1) * 18 + j]
                + hv.z * sw[(size_t)(k + 2) * 18 + j]
                + hv.w * sw[(size_t)(k + 3) * 18 + j];
    }
#pragma unroll
    for (int j = 0; j < 18; j++)
#pragma unroll
        for (int o = 16; o; o >>= 1) sacc[j] += __shfl_down_sync(0xffffffffu, sacc[j], o);

    __shared__ float sp[8][18];
    if (lane == 0)
#pragma unroll
        for (int j = 0; j < 18; j++) sp[w][j] = sacc[j];
    __syncthreads();

    if (tid == 0) {
        float g = 0.f;
#pragma unroll
        for (int i = 0; i < 8; i++) g += gs[i];
        g += gb2[0];
        out[n] = 1.f / (1.f + expf(-g));
    }
    if (tid < 18) {
        float s = sb[tid];
#pragma unroll
        for (int i = 0; i < 8; i++) s += sp[i][tid];
        out[10000 + n * 18 + tid] = s;
    }
}

// ---------------- launch ----------------
extern "C" void kernel_launch(void* const* d_in, const int* in_sizes, int n_in,
                              void* d_out, int out_size)
{
    const float* x      = (const float*)d_in[0];
    const int*   ei     = (const int*)d_in[1];
    const float* proj_w = (const float*)d_in[2];
    const float* W1     = (const float*)d_in[3];
    const float* b1     = (const float*)d_in[4];
    const float* W2     = (const float*)d_in[5];
    const float* b2     = (const float*)d_in[6];
    const float* gw1    = (const float*)d_in[7];
    const float* gb1    = (const float*)d_in[8];
    const float* gw2    = (const float*)d_in[9];
    const float* gb2    = (const float*)d_in[10];
    const float* sw     = (const float*)d_in[11];
    const float* sb     = (const float*)d_in[12];
    float* out = (float*)d_out;

    float *H, *C1, *G1;
    __half *Hh, *Sh, *WcT, *W2T, *G1T;
    int* degp;
    cudaGetSymbolAddress((void**)&H, g_H);
    cudaGetSymbolAddress((void**)&Hh, g_Hh);
    cudaGetSymbolAddress((void**)&Sh, g_Sh);
    cudaGetSymbolAddress((void**)&C1, g_C1);
    cudaGetSymbolAddress((void**)&WcT, g_WcatT);
    cudaGetSymbolAddress((void**)&W2T, g_W2T);
    cudaGetSymbolAddress((void**)&G1T, g_gw1T);
    cudaGetSymbolAddress((void**)&G1, g_G1);
    cudaGetSymbolAddress((void**)&degp, g_deg);

    // weight prep (transpose + fp16) + CSR build
    wcatT_kernel<<<dim3(2 * HID / 32, HID / 32, NLAYERS), dim3(32, 8)>>>(W1);
    w2T_kernel<<<dim3(HID / 32, HID / 32, NLAYERS), dim3(32, 8)>>>(W2);
    gw1T_kernel<<<dim3(256 / 32, HID / 32), dim3(32, 8)>>>(gw1);
    zero_deg_kernel<<<(NPAD + 255) / 256, 256>>>();
    hist_kernel<<<(EDGES + 255) / 256, 256>>>(ei);
    scan_kernel<<<1, 1024>>>();
    scatter_kernel<<<(EDGES + 255) / 256, 256>>>(ei);

    // initial embedding (writes fp32 H + fp16 mirror)
    proj_kernel<<<NPAD, 256>>>(x, proj_w);

    // layers
    for (int l = 0; l < NLAYERS; l++) {
        gemm_f16_kernel<<<dim3(2 * HID / 128, NPAD / 128), 256>>>(
            Hh, WcT + (size_t)l * 2 * HID * HID, C1, nullptr,
            HID, 2 * HID, 0, nullptr, nullptr);
        edge_agg_kernel<<<NPAD, 256>>>(b1 + (size_t)l * HID);
        gemm_f16_kernel<<<dim3(HID / 128, NPAD / 128), 256>>>(
            Sh, W2T + (size_t)l * HID * HID, H, Hh,
            HID, HID, 2, b2 + (size_t)l * HID, degp);
    }

    // ghost hidden: G1 = relu(h @ gw1 + gb1)
    gemm_f16_kernel<<<dim3(256 / 128, NPAD / 128), 256>>>(
        Hh, G1T, G1, nullptr, HID, 256, 3, gb1, nullptr);

    // heads + output
    final_kernel<<<NNODES, 256>>>(gw2, gb2, sw, sb, out);

    (void)in_sizes; (void)n_in; (void)out_size;
}

// round 15
// speedup vs baseline: 1.7012x; 1.0732x over previous
#include <cuda_runtime.h>
#include <cuda_fp16.h>
#include <math.h>
#include <stdint.h>

#define NNODES 10000
#define NPAD   10112      // 79 * 128
#define EDGES  80000
#define HID    1024
#define NLAYERS 4

// ---------------- scratch (static device globals: allowed) ----------------
__device__ float  g_H[(size_t)NPAD * HID];            // node features fp32 (output + heads)
__device__ __half g_Hh[(size_t)NPAD * HID];           // fp16 mirror of H (GEMM A operand)
__device__ __half g_Sh[(size_t)NPAD * HID];           // aggregated relu sums, fp16 (GEMM A operand)
__device__ float  g_C1[(size_t)NPAD * 2 * HID];       // [A | B] per node (fp32, feeds edge sums)
__device__ __half g_WcatT[(size_t)NLAYERS * 2 * HID * HID]; // [l][n(2048)][k(1024)] fp16 = ([W1a-W1b | W1b])^T
__device__ __half g_W2T[(size_t)NLAYERS * HID * HID];       // [l][n][k] fp16
__device__ __half g_gw1T[(size_t)256 * HID];                // [n][k] fp16
__device__ float  g_G1[(size_t)NPAD * 256];           // ghost hidden
__device__ int    g_deg[NPAD];
__device__ int    g_rowptr[NNODES + 1];
__device__ int    g_cursor[NNODES];
__device__ int    g_csrsrc[EDGES];

// ---------------- helpers ----------------
#define MMA_F16(d, a, b)                                               \
    asm volatile(                                                      \
        "mma.sync.aligned.m16n8k16.row.col.f32.f16.f16.f32 "           \
        "{%0,%1,%2,%3}, {%4,%5,%6,%7}, {%8,%9}, {%0,%1,%2,%3};\n"      \
        : "+f"(d[0]), "+f"(d[1]), "+f"(d[2]), "+f"(d[3])               \
        : "r"(a[0]), "r"(a[1]), "r"(a[2]), "r"(a[3]),                  \
          "r"(b[0]), "r"(b[1]))

#define LDSM_X4(r0, r1, r2, r3, addr)                                  \
    asm volatile(                                                      \
        "ldmatrix.sync.aligned.m8n8.x4.shared.b16 {%0,%1,%2,%3}, [%4];"\
        : "=r"(r0), "=r"(r1), "=r"(r2), "=r"(r3) : "r"(addr))

// ---------------- weight prep: transposed + fp16 ----------------
// WcatT[l][j][k] = (j<HID) ? W1[l][k][j] - W1[l][HID+k][j] : W1[l][HID+k][j-HID]
__global__ void wcatT_kernel(const float* __restrict__ W1) {
    __shared__ float t[32][33];
    int l = blockIdx.z;
    int j0 = blockIdx.x * 32, k0 = blockIdx.y * 32;
    const float* Wl = W1 + (size_t)l * 2 * HID * HID;
    int tx = threadIdx.x, ty = threadIdx.y;
    for (int kk = ty; kk < 32; kk += 8) {
        int k = k0 + kk, j = j0 + tx;
        float v;
        if (j < HID) v = Wl[(size_t)k * HID + j] - Wl[(size_t)(HID + k) * HID + j];
        else         v = Wl[(size_t)(HID + k) * HID + (j - HID)];
        t[kk][tx] = v;
    }
    __syncthreads();
    __half* dst = g_WcatT + (size_t)l * 2 * HID * HID;
    for (int jj = ty; jj < 32; jj += 8)
        dst[(size_t)(j0 + jj) * HID + k0 + tx] = __float2half_rn(t[tx][jj]);
}

__global__ void w2T_kernel(const float* __restrict__ W2) {
    __shared__ float t[32][33];
    int l = blockIdx.z;
    int n0 = blockIdx.x * 32, k0 = blockIdx.y * 32;
    const float* Wl = W2 + (size_t)l * HID * HID;
    int tx = threadIdx.x, ty = threadIdx.y;
    for (int kk = ty; kk < 32; kk += 8)
        t[kk][tx] = Wl[(size_t)(k0 + kk) * HID + n0 + tx];
    __syncthreads();
    __half* dst = g_W2T + (size_t)l * HID * HID;
    for (int nn = ty; nn < 32; nn += 8)
        dst[(size_t)(n0 + nn) * HID + k0 + tx] = __float2half_rn(t[tx][nn]);
}

__global__ void gw1T_kernel(const float* __restrict__ gw1) {
    __shared__ float t[32][33];
    int n0 = blockIdx.x * 32, k0 = blockIdx.y * 32;
    int tx = threadIdx.x, ty = threadIdx.y;
    for (int kk = ty; kk < 32; kk += 8)
        t[kk][tx] = gw1[(size_t)(k0 + kk) * 256 + n0 + tx];
    __syncthreads();
    for (int nn = ty; nn < 32; nn += 8)
        g_gw1T[(size_t)(n0 + nn) * HID + k0 + tx] = __float2half_rn(t[tx][nn]);
}

// ---------------- CSR build ----------------
__global__ void zero_deg_kernel() {
    int i = blockIdx.x * 256 + threadIdx.x;
    if (i < NPAD) g_deg[i] = 0;
}

__global__ void hist_kernel(const int* __restrict__ ei) {
    int e = blockIdx.x * 256 + threadIdx.x;
    if (e < EDGES) atomicAdd(&g_deg[ei[EDGES + e]], 1);
}

__global__ void scan_kernel() {
    const int CH = 10;
    int t = threadIdx.x;
    int base = t * CH;
    int loc[CH];
    int s = 0;
#pragma unroll
    for (int c = 0; c < CH; c++) {
        int idx = base + c;
        int v = (idx < NNODES) ? g_deg[idx] : 0;
        loc[c] = s;
        s += v;
    }
    __shared__ int sm[1024];
    sm[t] = s;
    __syncthreads();
    for (int off = 1; off < 1024; off <<= 1) {
        int v = (t >= off) ? sm[t - off] : 0;
        __syncthreads();
        sm[t] += v;
        __syncthreads();
    }
    int excl = (t > 0) ? sm[t - 1] : 0;
#pragma unroll
    for (int c = 0; c < CH; c++) {
        int idx = base + c;
        if (idx < NNODES) {
            int rp = excl + loc[c];
            g_rowptr[idx] = rp;
            g_cursor[idx] = rp;
        }
    }
    if (t == 1023) g_rowptr[NNODES] = sm[1023];
}

__global__ void scatter_kernel(const int* __restrict__ ei) {
    int e = blockIdx.x * 256 + threadIdx.x;
    if (e >= EDGES) return;
    int d = ei[EDGES + e];
    int s = ei[e];
    int p = atomicAdd(&g_cursor[d], 1);
    g_csrsrc[p] = s;
}

// ---------------- initial embedding ----------------
__global__ void proj_kernel(const float* __restrict__ x, const float* __restrict__ pw) {
    int n = blockIdx.x;
    int tid = threadIdx.x;
    float4* Hout = (float4*)(g_H + (size_t)n * HID);
    __half2* Hh = (__half2*)(g_Hh + (size_t)n * HID) + tid * 2;
    if (n >= NNODES) {
        Hout[tid] = make_float4(0.f, 0.f, 0.f, 0.f);
        Hh[0] = __half2half2(__float2half_rn(0.f));
        Hh[1] = __half2half2(__float2half_rn(0.f));
        return;
    }
    __shared__ float xs[18];
    if (tid < 18) xs[tid] = x[n * 18 + tid];
    __syncthreads();
    float4 acc = make_float4(0.f, 0.f, 0.f, 0.f);
#pragma unroll
    for (int t = 0; t < 18; t++) {
        float4 w = ((const float4*)(pw + (size_t)t * HID))[tid];
        float xv = xs[t];
        acc.x += xv * w.x;
        acc.y += xv * w.y;
        acc.z += xv * w.z;
        acc.w += xv * w.w;
    }
    float4 h;
    h.x = sinf(acc.x) * cosf(acc.x);
    h.y = sinf(acc.y) * cosf(acc.y);
    h.z = sinf(acc.z) * cosf(acc.z);
    h.w = sinf(acc.w) * cosf(acc.w);
    Hout[tid] = h;
    Hh[0] = __floats2half2_rn(h.x, h.y);
    Hh[1] = __floats2half2_rn(h.z, h.w);
}

// ---------------- edge aggregation: Sh[i] = fp16( sum_e relu(A[i] + B[src_e] + b1) ) ----------------
__global__ void edge_agg_kernel(const float* __restrict__ b1) {
    int i = blockIdx.x;
    int tid = threadIdx.x;
    __half2* Sout = (__half2*)(g_Sh + (size_t)i * HID) + tid * 2;
    if (i >= NNODES) {
        Sout[0] = __half2half2(__float2half_rn(0.f));
        Sout[1] = __half2half2(__float2half_rn(0.f));
        return;
    }
    float4 a = ((const float4*)(g_C1 + (size_t)i * 2 * HID))[tid];
    float4 bb = ((const float4*)b1)[tid];
    a.x += bb.x; a.y += bb.y; a.z += bb.z; a.w += bb.w;
    float4 acc = make_float4(0.f, 0.f, 0.f, 0.f);
    int p0 = g_rowptr[i], p1 = g_rowptr[i + 1];
    for (int p = p0; p < p1; p++) {
        int s = g_csrsrc[p];
        float4 b = ((const float4*)(g_C1 + (size_t)s * 2 * HID + HID))[tid];
        acc.x += fmaxf(a.x + b.x, 0.f);
        acc.y += fmaxf(a.y + b.y, 0.f);
        acc.z += fmaxf(a.z + b.z, 0.f);
        acc.w += fmaxf(a.w + b.w, 0.f);
    }
    Sout[0] = __floats2half2_rn(acc.x, acc.y);
    Sout[1] = __floats2half2_rn(acc.z, acc.w);
}

// ---------------- fp16 GEMM: C[M,N] = A[M,K] @ BT[N,K]^T ----------------
// A and BT both fp16 K-major. BM=128, BN=128, BK=32 (2 k16 slices), 256 threads
// (8 warps, warp tile 64x32), double-buffered padded smem, ldmatrix frag loads,
// fp32 accumulate.
// epi: 0 = none, 2 = relu(acc + deg[m]*bias[n]) [+ fp16 mirror Ch], 3 = relu(acc + bias[n])
#define HSTR 40   // halfs per smem row (32 data + 8 pad) -> conflict-free frags
#define STAGE_BYTES (128 * HSTR * 2)

__global__ __launch_bounds__(256) void gemm_f16_kernel(
    const __half* __restrict__ A, const __half* __restrict__ BT,
    float* __restrict__ C, __half* __restrict__ Ch,
    int K, int N, int epi, const float* __restrict__ bias, const int* __restrict__ deg)
{
    __shared__ __half As[2][128 * HSTR];   // 10KB per stage
    __shared__ __half Bs[2][128 * HSTR];   // 10KB per stage

    int tid = threadIdx.x;
    int warp = tid >> 5, lane = tid & 31;
    int lr = lane >> 2, lc = lane & 3;
    int moff = (warp >> 2) * 64, noff = (warp & 3) * 32;
    int gm0 = blockIdx.y * 128, gn0 = blockIdx.x * 128;

    // ldmatrix per-lane byte offsets (within a stage)
    // A tile mf (16x16 at row moff+mf*16, col 0): x4 matrices
    //   [m0-7@k0, m8-15@k0, m0-7@k8, m8-15@k8] -> regs a0..a3
    uint32_t aBase = (uint32_t)__cvta_generic_to_shared(&As[0][0]);
    uint32_t bBase = (uint32_t)__cvta_generic_to_shared(&Bs[0][0]);
    int sub = lane >> 3;             // 0..3 matrix group
    int l8 = lane & 7;
    uint32_t a_off[4];
#pragma unroll
    for (int mf = 0; mf < 4; mf++) {
        int row = moff + mf * 16 + l8 + (sub & 1) * 8;
        int col = (sub >> 1) * 8;
        a_off[mf] = (uint32_t)((row * HSTR + col) * 2);
    }
    // B pair p (nf=2p,2p+1): x4 matrices [nf0@k0, nf0@k8, nf1@k0, nf1@k8]
    uint32_t b_off[2];
#pragma unroll
    for (int p = 0; p < 2; p++) {
        int row = noff + p * 16 + (sub >> 1) * 8 + l8;
        int col = (sub & 1) * 8;
        b_off[p] = (uint32_t)((row * HSTR + col) * 2);
    }

    // load coords: tile is 128 rows x 32 halfs; 256 threads x 4 chunks of 4 halfs (8B)
    int rr[4], cc[4];
#pragma unroll
    for (int i = 0; i < 4; i++) {
        int idx = tid + i * 256;
        rr[i] = idx >> 3;
        cc[i] = (idx & 7) << 2;
    }

    float acc[4][4][4];
#pragma unroll
    for (int mf = 0; mf < 4; mf++)
#pragma unroll
        for (int nf = 0; nf < 4; nf++)
#pragma unroll
            for (int q = 0; q < 4; q++) acc[mf][nf][q] = 0.f;

    const int T = K >> 5;  // K=1024 -> 32 tiles
    uint2 ra[4], rb[4];

    // prologue: tile 0 -> regs -> stage 0
#pragma unroll
    for (int i = 0; i < 4; i++)
        ra[i] = *(const uint2*)(A + (size_t)(gm0 + rr[i]) * K + cc[i]);
#pragma unroll
    for (int i = 0; i < 4; i++)
        rb[i] = *(const uint2*)(BT + (size_t)(gn0 + rr[i]) * K + cc[i]);
#pragma unroll
    for (int i = 0; i < 4; i++) {
        *(uint2*)&As[0][rr[i] * HSTR + cc[i]] = ra[i];
        *(uint2*)&Bs[0][rr[i] * HSTR + cc[i]] = rb[i];
    }
    __syncthreads();

    for (int kt = 0; kt < T; kt++) {
        int cur = kt & 1, nxt = cur ^ 1;
        bool more = (kt + 1 < T);

        if (more) {
            int kg = (kt + 1) << 5;
#pragma unroll
            for (int i = 0; i < 4; i++)
                ra[i] = *(const uint2*)(A + (size_t)(gm0 + rr[i]) * K + kg + cc[i]);
#pragma unroll
            for (int i = 0; i < 4; i++)
                rb[i] = *(const uint2*)(BT + (size_t)(gn0 + rr[i]) * K + kg + cc[i]);
        }

        uint32_t aStage = aBase + cur * STAGE_BYTES;
        uint32_t bStage = bBase + cur * STAGE_BYTES;
#pragma unroll
        for (int ks = 0; ks < 2; ks++) {
            uint32_t kadd = (uint32_t)(ks * 16 * 2);  // +16 halfs
            unsigned a[4][4], b[4][2];
#pragma unroll
            for (int mf = 0; mf < 4; mf++)
                LDSM_X4(a[mf][0], a[mf][1], a[mf][2], a[mf][3],
                        aStage + a_off[mf] + kadd);
            LDSM_X4(b[0][0], b[0][1], b[1][0], b[1][1], bStage + b_off[0] + kadd);
            LDSM_X4(b[2][0], b[2][1], b[3][0], b[3][1], bStage + b_off[1] + kadd);
#pragma unroll
            for (int mf = 0; mf < 4; mf++)
#pragma unroll
                for (int nf = 0; nf < 4; nf++)
                    MMA_F16(acc[mf][nf], a[mf], b[nf]);
        }

        if (more) {
#pragma unroll
            for (int i = 0; i < 4; i++) {
                *(uint2*)&As[nxt][rr[i] * HSTR + cc[i]] = ra[i];
                *(uint2*)&Bs[nxt][rr[i] * HSTR + cc[i]] = rb[i];
            }
        }
        __syncthreads();
    }

    // epilogue
#pragma unroll
    for (int mf = 0; mf < 4; mf++) {
        int r = gm0 + moff + mf * 16 + lr;
        float d0 = 0.f, d1 = 0.f;
        if (epi == 2) { d0 = (float)deg[r]; d1 = (float)deg[r + 8]; }
#pragma unroll
        for (int nf = 0; nf < 4; nf++) {
            int c = gn0 + noff + nf * 8 + 2 * lc;
            float2 v0 = make_float2(acc[mf][nf][0], acc[mf][nf][1]);
            float2 v1 = make_float2(acc[mf][nf][2], acc[mf][nf][3]);
            if (epi != 0) {
                float b0 = bias[c], b1v = bias[c + 1];
                if (epi == 2) {
                    v0.x += d0 * b0; v0.y += d0 * b1v;
                    v1.x += d1 * b0; v1.y += d1 * b1v;
                } else {
                    v0.x += b0; v0.y += b1v;
                    v1.x += b0; v1.y += b1v;
                }
                v0.x = fmaxf(v0.x, 0.f); v0.y = fmaxf(v0.y, 0.f);
                v1.x = fmaxf(v1.x, 0.f); v1.y = fmaxf(v1.y, 0.f);
            }
            *(float2*)(C + (size_t)r * N + c) = v0;
            *(float2*)(C + (size_t)(r + 8) * N + c) = v1;
            if (epi == 2) {
                *(__half2*)(Ch + (size_t)r * N + c) = __floats2half2_rn(v0.x, v0.y);
                *(__half2*)(Ch + (size_t)(r + 8) * N + c) = __floats2half2_rn(v1.x, v1.y);
            }
        }
    }
}

// ---------------- final heads ----------------
// out: [0,10000) ghost, [10000,190000) stable (N x 18), [190000,...) h (N x 1024)
__global__ void final_kernel(const float* __restrict__ gw2, const float* __restrict__ gb2,
                             const float* __restrict__ sw, const float* __restrict__ sb,
                             float* __restrict__ out)
{
    int n = blockIdx.x;
    int tid = threadIdx.x;
    int lane = tid & 31, w = tid >> 5;

    float v = g_G1[(size_t)n * 256 + tid] * gw2[tid];
#pragma unroll
    for (int o = 16; o; o >>= 1) v += __shfl_down_sync(0xffffffffu, v, o);
    __shared__ float gs[8];
    if (lane == 0) gs[w] = v;

    float4 hv = ((const float4*)(g_H + (size_t)n * HID))[tid];
    ((float4*)(out + 190000 + (size_t)n * HID))[tid] = hv;

    int k = tid * 4;
    float sacc[18];
#pragma unroll
    for (int j = 0; j < 18; j++) {
        sacc[j] = hv.x * sw[(size_t)(k + 0) * 18 + j]
                + hv.y * sw[(size_t)(k + 1) * 18 + j]
                + hv.z * sw[(size_t)(k + 2) * 18 + j]
                + hv.w * sw[(size_t)(k + 3) * 18 + j];
    }
#pragma unroll
    for (int j = 0; j < 18; j++)
#pragma unroll
        for (int o = 16; o; o >>= 1) sacc[j] += __shfl_down_sync(0xffffffffu, sacc[j], o);

    __shared__ float sp[8][18];
    if (lane == 0)
#pragma unroll
        for (int j = 0; j < 18; j++) sp[w][j] = sacc[j];
    __syncthreads();

    if (tid == 0) {
        float g = 0.f;
#pragma unroll
        for (int i = 0; i < 8; i++) g += gs[i];
        g += gb2[0];
        out[n] = 1.f / (1.f + expf(-g));
    }
    if (tid < 18) {
        float s = sb[tid];
#pragma unroll
        for (int i = 0; i < 8; i++) s += sp[i][tid];
        out[10000 + n * 18 + tid] = s;
    }
}

// ---------------- launch ----------------
extern "C" void kernel_launch(void* const* d_in, const int* in_sizes, int n_in,
                              void* d_out, int out_size)
{
    const float* x      = (const float*)d_in[0];
    const int*   ei     = (const int*)d_in[1];
    const float* proj_w = (const float*)d_in[2];
    const float* W1     = (const float*)d_in[3];
    const float* b1     = (const float*)d_in[4];
    const float* W2     = (const float*)d_in[5];
    const float* b2     = (const float*)d_in[6];
    const float* gw1    = (const float*)d_in[7];
    const float* gb1    = (const float*)d_in[8];
    const float* gw2    = (const float*)d_in[9];
    const float* gb2    = (const float*)d_in[10];
    const float* sw     = (const float*)d_in[11];
    const float* sb     = (const float*)d_in[12];
    float* out = (float*)d_out;

    float *H, *C1, *G1;
    __half *Hh, *Sh, *WcT, *W2T, *G1T;
    int* degp;
    cudaGetSymbolAddress((void**)&H, g_H);
    cudaGetSymbolAddress((void**)&Hh, g_Hh);
    cudaGetSymbolAddress((void**)&Sh, g_Sh);
    cudaGetSymbolAddress((void**)&C1, g_C1);
    cudaGetSymbolAddress((void**)&WcT, g_WcatT);
    cudaGetSymbolAddress((void**)&W2T, g_W2T);
    cudaGetSymbolAddress((void**)&G1T, g_gw1T);
    cudaGetSymbolAddress((void**)&G1, g_G1);
    cudaGetSymbolAddress((void**)&degp, g_deg);

    // weight prep (transpose + fp16) + CSR build
    wcatT_kernel<<<dim3(2 * HID / 32, HID / 32, NLAYERS), dim3(32, 8)>>>(W1);
    w2T_kernel<<<dim3(HID / 32, HID / 32, NLAYERS), dim3(32, 8)>>>(W2);
    gw1T_kernel<<<dim3(256 / 32, HID / 32), dim3(32, 8)>>>(gw1);
    zero_deg_kernel<<<(NPAD + 255) / 256, 256>>>();
    hist_kernel<<<(EDGES + 255) / 256, 256>>>(ei);
    scan_kernel<<<1, 1024>>>();
    scatter_kernel<<<(EDGES + 255) / 256, 256>>>(ei);

    // initial embedding (writes fp32 H + fp16 mirror)
    proj_kernel<<<NPAD, 256>>>(x, proj_w);

    // layers
    for (int l = 0; l < NLAYERS; l++) {
        gemm_f16_kernel<<<dim3(2 * HID / 128, NPAD / 128), 256>>>(
            Hh, WcT + (size_t)l * 2 * HID * HID, C1, nullptr,
            HID, 2 * HID, 0, nullptr, nullptr);
        edge_agg_kernel<<<NPAD, 256>>>(b1 + (size_t)l * HID);
        gemm_f16_kernel<<<dim3(HID / 128, NPAD / 128), 256>>>(
            Sh, W2T + (size_t)l * HID * HID, H, Hh,
            HID, HID, 2, b2 + (size_t)l * HID, degp);
    }

    // ghost hidden: G1 = relu(h @ gw1 + gb1)
    gemm_f16_kernel<<<dim3(256 / 128, NPAD / 128), 256>>>(
        Hh, G1T, G1, nullptr, HID, 256, 3, gb1, nullptr);

    // heads + output
    final_kernel<<<NNODES, 256>>>(gw2, gb2, sw, sb, out);

    (void)in_sizes; (void)n_in; (void)out_size;
}

// round 16
// speedup vs baseline: 1.8416x; 1.0825x over previous
#include <cuda_runtime.h>
#include <cuda_fp16.h>
#include <math.h>
#include <stdint.h>

#define NNODES 10000
#define NPAD   10112      // 79 * 128
#define EDGES  80000
#define HID    1024
#define NLAYERS 4

// ---------------- scratch (static device globals: allowed) ----------------
__device__ float  g_H[(size_t)NPAD * HID];            // node features fp32 (output + heads)
__device__ __half g_Hh[(size_t)NPAD * HID];           // fp16 mirror of H (GEMM A operand)
__device__ __half g_Sh[(size_t)NPAD * HID];           // aggregated relu sums, fp16 (GEMM A operand)
__device__ float  g_C1[(size_t)NPAD * 2 * HID];       // [A | B] per node (fp32, feeds edge sums)
__device__ __half g_WcatT[(size_t)NLAYERS * 2 * HID * HID]; // [l][n(2048)][k(1024)] fp16 = ([W1a-W1b | W1b])^T
__device__ __half g_W2T[(size_t)NLAYERS * HID * HID];       // [l][n][k] fp16
__device__ __half g_gw1T[(size_t)256 * HID];                // [n][k] fp16
__device__ float  g_G1[(size_t)NPAD * 256];           // ghost hidden
__device__ int    g_deg[NPAD];
__device__ int    g_rowptr[NNODES + 1];
__device__ int    g_cursor[NNODES];
__device__ int    g_csrsrc[EDGES];

// ---------------- helpers ----------------
#define MMA_F16(d, a, b)                                               \
    asm volatile(                                                      \
        "mma.sync.aligned.m16n8k16.row.col.f32.f16.f16.f32 "           \
        "{%0,%1,%2,%3}, {%4,%5,%6,%7}, {%8,%9}, {%0,%1,%2,%3};\n"      \
        : "+f"(d[0]), "+f"(d[1]), "+f"(d[2]), "+f"(d[3])               \
        : "r"(a[0]), "r"(a[1]), "r"(a[2]), "r"(a[3]),                  \
          "r"(b[0]), "r"(b[1]))

#define LDSM_X4(r0, r1, r2, r3, addr)                                  \
    asm volatile(                                                      \
        "ldmatrix.sync.aligned.m8n8.x4.shared.b16 {%0,%1,%2,%3}, [%4];"\
        : "=r"(r0), "=r"(r1), "=r"(r2), "=r"(r3) : "r"(addr))

#define CP_ASYNC_16(dst, src)                                          \
    asm volatile("cp.async.cg.shared.global [%0], [%1], 16;"           \
                 :: "r"(dst), "l"(src) : "memory")

#define CP_COMMIT() asm volatile("cp.async.commit_group;" ::: "memory")
#define CP_WAIT0()  asm volatile("cp.async.wait_group 0;" ::: "memory")

// ---------------- weight prep: transposed + fp16 ----------------
// WcatT[l][j][k] = (j<HID) ? W1[l][k][j] - W1[l][HID+k][j] : W1[l][HID+k][j-HID]
__global__ void wcatT_kernel(const float* __restrict__ W1) {
    __shared__ float t[32][33];
    int l = blockIdx.z;
    int j0 = blockIdx.x * 32, k0 = blockIdx.y * 32;
    const float* Wl = W1 + (size_t)l * 2 * HID * HID;
    int tx = threadIdx.x, ty = threadIdx.y;
    for (int kk = ty; kk < 32; kk += 8) {
        int k = k0 + kk, j = j0 + tx;
        float v;
        if (j < HID) v = Wl[(size_t)k * HID + j] - Wl[(size_t)(HID + k) * HID + j];
        else         v = Wl[(size_t)(HID + k) * HID + (j - HID)];
        t[kk][tx] = v;
    }
    __syncthreads();
    __half* dst = g_WcatT + (size_t)l * 2 * HID * HID;
    for (int jj = ty; jj < 32; jj += 8)
        dst[(size_t)(j0 + jj) * HID + k0 + tx] = __float2half_rn(t[tx][jj]);
}

__global__ void w2T_kernel(const float* __restrict__ W2) {
    __shared__ float t[32][33];
    int l = blockIdx.z;
    int n0 = blockIdx.x * 32, k0 = blockIdx.y * 32;
    const float* Wl = W2 + (size_t)l * HID * HID;
    int tx = threadIdx.x, ty = threadIdx.y;
    for (int kk = ty; kk < 32; kk += 8)
        t[kk][tx] = Wl[(size_t)(k0 + kk) * HID + n0 + tx];
    __syncthreads();
    __half* dst = g_W2T + (size_t)l * HID * HID;
    for (int nn = ty; nn < 32; nn += 8)
        dst[(size_t)(n0 + nn) * HID + k0 + tx] = __float2half_rn(t[tx][nn]);
}

__global__ void gw1T_kernel(const float* __restrict__ gw1) {
    __shared__ float t[32][33];
    int n0 = blockIdx.x * 32, k0 = blockIdx.y * 32;
    int tx = threadIdx.x, ty = threadIdx.y;
    for (int kk = ty; kk < 32; kk += 8)
        t[kk][tx] = gw1[(size_t)(k0 + kk) * 256 + n0 + tx];
    __syncthreads();
    for (int nn = ty; nn < 32; nn += 8)
        g_gw1T[(size_t)(n0 + nn) * HID + k0 + tx] = __float2half_rn(t[tx][nn]);
}

// ---------------- CSR build ----------------
__global__ void zero_deg_kernel() {
    int i = blockIdx.x * 256 + threadIdx.x;
    if (i < NPAD) g_deg[i] = 0;
}

__global__ void hist_kernel(const int* __restrict__ ei) {
    int e = blockIdx.x * 256 + threadIdx.x;
    if (e < EDGES) atomicAdd(&g_deg[ei[EDGES + e]], 1);
}

__global__ void scan_kernel() {
    const int CH = 10;
    int t = threadIdx.x;
    int base = t * CH;
    int loc[CH];
    int s = 0;
#pragma unroll
    for (int c = 0; c < CH; c++) {
        int idx = base + c;
        int v = (idx < NNODES) ? g_deg[idx] : 0;
        loc[c] = s;
        s += v;
    }
    __shared__ int sm[1024];
    sm[t] = s;
    __syncthreads();
    for (int off = 1; off < 1024; off <<= 1) {
        int v = (t >= off) ? sm[t - off] : 0;
        __syncthreads();
        sm[t] += v;
        __syncthreads();
    }
    int excl = (t > 0) ? sm[t - 1] : 0;
#pragma unroll
    for (int c = 0; c < CH; c++) {
        int idx = base + c;
        if (idx < NNODES) {
            int rp = excl + loc[c];
            g_rowptr[idx] = rp;
            g_cursor[idx] = rp;
        }
    }
    if (t == 1023) g_rowptr[NNODES] = sm[1023];
}

__global__ void scatter_kernel(const int* __restrict__ ei) {
    int e = blockIdx.x * 256 + threadIdx.x;
    if (e >= EDGES) return;
    int d = ei[EDGES + e];
    int s = ei[e];
    int p = atomicAdd(&g_cursor[d], 1);
    g_csrsrc[p] = s;
}

// ---------------- initial embedding ----------------
__global__ void proj_kernel(const float* __restrict__ x, const float* __restrict__ pw) {
    int n = blockIdx.x;
    int tid = threadIdx.x;
    float4* Hout = (float4*)(g_H + (size_t)n * HID);
    __half2* Hh = (__half2*)(g_Hh + (size_t)n * HID) + tid * 2;
    if (n >= NNODES) {
        Hout[tid] = make_float4(0.f, 0.f, 0.f, 0.f);
        Hh[0] = __half2half2(__float2half_rn(0.f));
        Hh[1] = __half2half2(__float2half_rn(0.f));
        return;
    }
    __shared__ float xs[18];
    if (tid < 18) xs[tid] = x[n * 18 + tid];
    __syncthreads();
    float4 acc = make_float4(0.f, 0.f, 0.f, 0.f);
#pragma unroll
    for (int t = 0; t < 18; t++) {
        float4 w = ((const float4*)(pw + (size_t)t * HID))[tid];
        float xv = xs[t];
        acc.x += xv * w.x;
        acc.y += xv * w.y;
        acc.z += xv * w.z;
        acc.w += xv * w.w;
    }
    float4 h;
    h.x = sinf(acc.x) * cosf(acc.x);
    h.y = sinf(acc.y) * cosf(acc.y);
    h.z = sinf(acc.z) * cosf(acc.z);
    h.w = sinf(acc.w) * cosf(acc.w);
    Hout[tid] = h;
    Hh[0] = __floats2half2_rn(h.x, h.y);
    Hh[1] = __floats2half2_rn(h.z, h.w);
}

// ---------------- edge aggregation: Sh[i] = fp16( sum_e relu(A[i] + B[src_e] + b1) ) ----------------
__global__ void edge_agg_kernel(const float* __restrict__ b1) {
    int i = blockIdx.x;
    int tid = threadIdx.x;
    __half2* Sout = (__half2*)(g_Sh + (size_t)i * HID) + tid * 2;
    if (i >= NNODES) {
        Sout[0] = __half2half2(__float2half_rn(0.f));
        Sout[1] = __half2half2(__float2half_rn(0.f));
        return;
    }
    float4 a = ((const float4*)(g_C1 + (size_t)i * 2 * HID))[tid];
    float4 bb = ((const float4*)b1)[tid];
    a.x += bb.x; a.y += bb.y; a.z += bb.z; a.w += bb.w;
    float4 acc = make_float4(0.f, 0.f, 0.f, 0.f);
    int p0 = g_rowptr[i], p1 = g_rowptr[i + 1];
    for (int p = p0; p < p1; p++) {
        int s = g_csrsrc[p];
        float4 b = ((const float4*)(g_C1 + (size_t)s * 2 * HID + HID))[tid];
        acc.x += fmaxf(a.x + b.x, 0.f);
        acc.y += fmaxf(a.y + b.y, 0.f);
        acc.z += fmaxf(a.z + b.z, 0.f);
        acc.w += fmaxf(a.w + b.w, 0.f);
    }
    Sout[0] = __floats2half2_rn(acc.x, acc.y);
    Sout[1] = __floats2half2_rn(acc.z, acc.w);
}

// ---------------- fp16 GEMM: C[M,N] = A[M,K] @ BT[N,K]^T ----------------
// A and BT both fp16 K-major. BM=128, BN=128, BK=32 (2 k16 slices), 256 threads
// (8 warps, warp tile 64x32), 2-stage cp.async pipeline, ldmatrix frag loads,
// fp32 accumulate.
// epi: 0 = none, 2 = relu(acc + deg[m]*bias[n]) [+ fp16 mirror Ch], 3 = relu(acc + bias[n])
#define HSTR 40   // halfs per smem row (32 data + 8 pad) -> conflict-free frags
#define STAGE_BYTES (128 * HSTR * 2)

__global__ __launch_bounds__(256) void gemm_f16_kernel(
    const __half* __restrict__ A, const __half* __restrict__ BT,
    float* __restrict__ C, __half* __restrict__ Ch,
    int K, int N, int epi, const float* __restrict__ bias, const int* __restrict__ deg)
{
    __shared__ __half As[2][128 * HSTR];   // 10KB per stage
    __shared__ __half Bs[2][128 * HSTR];   // 10KB per stage

    int tid = threadIdx.x;
    int warp = tid >> 5, lane = tid & 31;
    int lr = lane >> 2, lc = lane & 3;
    int moff = (warp >> 2) * 64, noff = (warp & 3) * 32;
    int gm0 = blockIdx.y * 128, gn0 = blockIdx.x * 128;

    uint32_t aBase = (uint32_t)__cvta_generic_to_shared(&As[0][0]);
    uint32_t bBase = (uint32_t)__cvta_generic_to_shared(&Bs[0][0]);

    // ldmatrix per-lane byte offsets (within a stage)
    int sub = lane >> 3;             // 0..3 matrix group
    int l8 = lane & 7;
    uint32_t a_off[4];
#pragma unroll
    for (int mf = 0; mf < 4; mf++) {
        int row = moff + mf * 16 + l8 + (sub & 1) * 8;
        int col = (sub >> 1) * 8;
        a_off[mf] = (uint32_t)((row * HSTR + col) * 2);
    }
    uint32_t b_off[2];
#pragma unroll
    for (int p = 0; p < 2; p++) {
        int row = noff + p * 16 + (sub >> 1) * 8 + l8;
        int col = (sub & 1) * 8;
        b_off[p] = (uint32_t)((row * HSTR + col) * 2);
    }

    // cp.async coords: tile 128 rows x 32 halfs = 512 chunks of 16B (8 halfs);
    // 256 threads x 2 chunks. r = idx>>2, c8 = (idx&3)*8
    int rr[2], cc[2];
    uint32_t sa_d[2], sb_d[2];
#pragma unroll
    for (int i = 0; i < 2; i++) {
        int idx = tid + i * 256;
        rr[i] = idx >> 2;
        cc[i] = (idx & 3) << 3;
        sa_d[i] = aBase + (uint32_t)((rr[i] * HSTR + cc[i]) * 2);
        sb_d[i] = bBase + (uint32_t)((rr[i] * HSTR + cc[i]) * 2);
    }
    const __half* Arow0 = A + (size_t)(gm0 + rr[0]) * K + cc[0];
    const __half* Arow1 = A + (size_t)(gm0 + rr[1]) * K + cc[1];
    const __half* Brow0 = BT + (size_t)(gn0 + rr[0]) * K + cc[0];
    const __half* Brow1 = BT + (size_t)(gn0 + rr[1]) * K + cc[1];

    float acc[4][4][4];
#pragma unroll
    for (int mf = 0; mf < 4; mf++)
#pragma unroll
        for (int nf = 0; nf < 4; nf++)
#pragma unroll
            for (int q = 0; q < 4; q++) acc[mf][nf][q] = 0.f;

    const int T = K >> 5;  // K=1024 -> 32 tiles

    // prologue: stage 0
    CP_ASYNC_16(sa_d[0], Arow0);
    CP_ASYNC_16(sa_d[1], Arow1);
    CP_ASYNC_16(sb_d[0], Brow0);
    CP_ASYNC_16(sb_d[1], Brow1);
    CP_COMMIT();

    for (int kt = 0; kt < T; kt++) {
        int cur = kt & 1, nxt = cur ^ 1;
        bool more = (kt + 1 < T);

        CP_WAIT0();          // stage cur arrived (only this group outstanding)
        __syncthreads();     // visible to all; all warps done with stage nxt

        if (more) {
            int kg = (kt + 1) << 5;
            uint32_t soff = (uint32_t)(nxt * STAGE_BYTES);
            CP_ASYNC_16(sa_d[0] + soff, Arow0 + kg);
            CP_ASYNC_16(sa_d[1] + soff, Arow1 + kg);
            CP_ASYNC_16(sb_d[0] + soff, Brow0 + kg);
            CP_ASYNC_16(sb_d[1] + soff, Brow1 + kg);
            CP_COMMIT();
        }

        uint32_t aStage = aBase + cur * STAGE_BYTES;
        uint32_t bStage = bBase + cur * STAGE_BYTES;
#pragma unroll
        for (int ks = 0; ks < 2; ks++) {
            uint32_t kadd = (uint32_t)(ks * 16 * 2);  // +16 halfs
            unsigned a[4][4], b[4][2];
#pragma unroll
            for (int mf = 0; mf < 4; mf++)
                LDSM_X4(a[mf][0], a[mf][1], a[mf][2], a[mf][3],
                        aStage + a_off[mf] + kadd);
            LDSM_X4(b[0][0], b[0][1], b[1][0], b[1][1], bStage + b_off[0] + kadd);
            LDSM_X4(b[2][0], b[2][1], b[3][0], b[3][1], bStage + b_off[1] + kadd);
#pragma unroll
            for (int mf = 0; mf < 4; mf++)
#pragma unroll
                for (int nf = 0; nf < 4; nf++)
                    MMA_F16(acc[mf][nf], a[mf], b[nf]);
        }
    }

    // epilogue
#pragma unroll
    for (int mf = 0; mf < 4; mf++) {
        int r = gm0 + moff + mf * 16 + lr;
        float d0 = 0.f, d1 = 0.f;
        if (epi == 2) { d0 = (float)deg[r]; d1 = (float)deg[r + 8]; }
#pragma unroll
        for (int nf = 0; nf < 4; nf++) {
            int c = gn0 + noff + nf * 8 + 2 * lc;
            float2 v0 = make_float2(acc[mf][nf][0], acc[mf][nf][1]);
            float2 v1 = make_float2(acc[mf][nf][2], acc[mf][nf][3]);
            if (epi != 0) {
                float b0 = bias[c], b1v = bias[c + 1];
                if (epi == 2) {
                    v0.x += d0 * b0; v0.y += d0 * b1v;
                    v1.x += d1 * b0; v1.y += d1 * b1v;
                } else {
                    v0.x += b0; v0.y += b1v;
                    v1.x += b0; v1.y += b1v;
                }
                v0.x = fmaxf(v0.x, 0.f); v0.y = fmaxf(v0.y, 0.f);
                v1.x = fmaxf(v1.x, 0.f); v1.y = fmaxf(v1.y, 0.f);
            }
            *(float2*)(C + (size_t)r * N + c) = v0;
            *(float2*)(C + (size_t)(r + 8) * N + c) = v1;
            if (epi == 2) {
                *(__half2*)(Ch + (size_t)r * N + c) = __floats2half2_rn(v0.x, v0.y);
                *(__half2*)(Ch + (size_t)(r + 8) * N + c) = __floats2half2_rn(v1.x, v1.y);
            }
        }
    }
}

// ---------------- final heads ----------------
// out: [0,10000) ghost, [10000,190000) stable (N x 18), [190000,...) h (N x 1024)
__global__ void final_kernel(const float* __restrict__ gw2, const float* __restrict__ gb2,
                             const float* __restrict__ sw, const float* __restrict__ sb,
                             float* __restrict__ out)
{
    int n = blockIdx.x;
    int tid = threadIdx.x;
    int lane = tid & 31, w = tid >> 5;

    float v = g_G1[(size_t)n * 256 + tid] * gw2[tid];
#pragma unroll
    for (int o = 16; o; o >>= 1) v += __shfl_down_sync(0xffffffffu, v, o);
    __shared__ float gs[8];
    if (lane == 0) gs[w] = v;

    float4 hv = ((const float4*)(g_H + (size_t)n * HID))[tid];
    ((float4*)(out + 190000 + (size_t)n * HID))[tid] = hv;

    int k = tid * 4;
    float sacc[18];
#pragma unroll
    for (int j = 0; j < 18; j++) {
        sacc[j] = hv.x * sw[(size_t)(k + 0) * 18 + j]
                + hv.y * sw[(size_t)(k + 1) * 18 + j]
                + hv.z * sw[(size_t)(k + 2) * 18 + j]
                + hv.w * sw[(size_t)(k + 3) * 18 + j];
    }
#pragma unroll
    for (int j = 0; j < 18; j++)
#pragma unroll
        for (int o = 16; o; o >>= 1) sacc[j] += __shfl_down_sync(0xffffffffu, sacc[j], o);

    __shared__ float sp[8][18];
    if (lane == 0)
#pragma unroll
        for (int j = 0; j < 18; j++) sp[w][j] = sacc[j];
    __syncthreads();

    if (tid == 0) {
        float g = 0.f;
#pragma unroll
        for (int i = 0; i < 8; i++) g += gs[i];
        g += gb2[0];
        out[n] = 1.f / (1.f + expf(-g));
    }
    if (tid < 18) {
        float s = sb[tid];
#pragma unroll
        for (int i = 0; i < 8; i++) s += sp[i][tid];
        out[10000 + n * 18 + tid] = s;
    }
}

// ---------------- launch ----------------
extern "C" void kernel_launch(void* const* d_in, const int* in_sizes, int n_in,
                              void* d_out, int out_size)
{
    const float* x      = (const float*)d_in[0];
    const int*   ei     = (const int*)d_in[1];
    const float* proj_w = (const float*)d_in[2];
    const float* W1     = (const float*)d_in[3];
    const float* b1     = (const float*)d_in[4];
    const float* W2     = (const float*)d_in[5];
    const float* b2     = (const float*)d_in[6];
    const float* gw1    = (const float*)d_in[7];
    const float* gb1    = (const float*)d_in[8];
    const float* gw2    = (const float*)d_in[9];
    const float* gb2    = (const float*)d_in[10];
    const float* sw     = (const float*)d_in[11];
    const float* sb     = (const float*)d_in[12];
    float* out = (float*)d_out;

    float *H, *C1, *G1;
    __half *Hh, *Sh, *WcT, *W2T, *G1T;
    int* degp;
    cudaGetSymbolAddress((void**)&H, g_H);
    cudaGetSymbolAddress((void**)&Hh, g_Hh);
    cudaGetSymbolAddress((void**)&Sh, g_Sh);
    cudaGetSymbolAddress((void**)&C1, g_C1);
    cudaGetSymbolAddress((void**)&WcT, g_WcatT);
    cudaGetSymbolAddress((void**)&W2T, g_W2T);
    cudaGetSymbolAddress((void**)&G1T, g_gw1T);
    cudaGetSymbolAddress((void**)&G1, g_G1);
    cudaGetSymbolAddress((void**)&degp, g_deg);

    // weight prep (transpose + fp16) + CSR build
    wcatT_kernel<<<dim3(2 * HID / 32, HID / 32, NLAYERS), dim3(32, 8)>>>(W1);
    w2T_kernel<<<dim3(HID / 32, HID / 32, NLAYERS), dim3(32, 8)>>>(W2);
    gw1T_kernel<<<dim3(256 / 32, HID / 32), dim3(32, 8)>>>(gw1);
    zero_deg_kernel<<<(NPAD + 255) / 256, 256>>>();
    hist_kernel<<<(EDGES + 255) / 256, 256>>>(ei);
    scan_kernel<<<1, 1024>>>();
    scatter_kernel<<<(EDGES + 255) / 256, 256>>>(ei);

    // initial embedding (writes fp32 H + fp16 mirror)
    proj_kernel<<<NPAD, 256>>>(x, proj_w);

    // layers
    for (int l = 0; l < NLAYERS; l++) {
        gemm_f16_kernel<<<dim3(2 * HID / 128, NPAD / 128), 256>>>(
            Hh, WcT + (size_t)l * 2 * HID * HID, C1, nullptr,
            HID, 2 * HID, 0, nullptr, nullptr);
        edge_agg_kernel<<<NPAD, 256>>>(b1 + (size_t)l * HID);
        gemm_f16_kernel<<<dim3(HID / 128, NPAD / 128), 256>>>(
            Sh, W2T + (size_t)l * HID * HID, H, Hh,
            HID, HID, 2, b2 + (size_t)l * HID, degp);
    }

    // ghost hidden: G1 = relu(h @ gw1 + gb1)
    gemm_f16_kernel<<<dim3(256 / 128, NPAD / 128), 256>>>(
        Hh, G1T, G1, nullptr, HID, 256, 3, gb1, nullptr);

    // heads + output
    final_kernel<<<NNODES, 256>>>(gw2, gb2, sw, sb, out);

    (void)in_sizes; (void)n_in; (void)out_size;
}